// round 11
// baseline (speedup 1.0000x reference)
#include <cuda_runtime.h>
#include <cuda_bf16.h>
#include <cstdint>

#define N_NODES 50000
#define N_EDGES 800000
#define N_EL    100000
#define NSCAN_BLOCKS ((N_NODES + 255) / 256)   // 196

// ---------------- scratch (device globals; no allocation allowed) ----------------
// INVARIANT: g_degi, g_scanstate, g_scandone are zero at the start of every run.
// (zero-initialized at module load; fill_csr_kernel restores them each run)
__device__ int      g_degi     [N_NODES];
__device__ uint32_t g_scanstate[NSCAN_BLOCKS];
__device__ int      g_scandone;
__device__ int      g_rowptr   [N_NODES + 1];
__device__ int      g_csr      [N_EDGES];      // BYTE offsets: src*256
__device__ float g_dinv[N_NODES];
__device__ float g_h1  [N_NODES * 64];         // scaled: h1*dinv[row]
__device__ float g_h2  [N_NODES * 64];         // scaled: h2*dinv[row]
__device__ float g_z2  [N_NODES * 64];
// pre-split bf16 operand arrays
__device__ __nv_bfloat16 g_xhi [N_NODES * 128];
__device__ __nv_bfloat16 g_xlo [N_NODES * 128];
__device__ __nv_bfloat16 g_z1hi[N_NODES * 64];
__device__ __nv_bfloat16 g_z1lo[N_NODES * 64];
__device__ __nv_bfloat16 g_w1hi[128 * 64];
__device__ __nv_bfloat16 g_w1lo[128 * 64];
__device__ __nv_bfloat16 g_w2hi[64 * 64];
__device__ __nv_bfloat16 g_w2lo[64 * 64];

// ---------------- helpers ----------------
__device__ __forceinline__ uint32_t smem_u32(const void* p) {
    uint32_t a;
    asm("{ .reg .u64 t; cvta.to.shared.u64 t, %1; cvt.u32.u64 %0, t; }" : "=r"(a) : "l"(p));
    return a;
}
__device__ __forceinline__ uint32_t pack_bf16(float x, float y) {
    __nv_bfloat162 t = __floats2bfloat162_rn(x, y);
    return *(uint32_t*)&t;
}
__device__ __forceinline__ float bf_hi(float x) {
    return __bfloat162float(__float2bfloat16_rn(x));
}
__device__ __forceinline__ void cp16(uint32_t dst, const void* src, uint32_t sz) {
    asm volatile("cp.async.ca.shared.global [%0], [%1], 16, %2;"
                 :: "r"(dst), "l"(src), "r"(sz) : "memory");
}
__device__ __forceinline__ void cp_commit_wait() {
    asm volatile("cp.async.commit_group;");
    asm volatile("cp.async.wait_group 0;" ::: "memory");
}
__device__ __forceinline__ void ldsm_x4(uint32_t* r, uint32_t addr) {
    asm volatile("ldmatrix.sync.aligned.m8n8.x4.shared.b16 {%0,%1,%2,%3}, [%4];"
                 : "=r"(r[0]), "=r"(r[1]), "=r"(r[2]), "=r"(r[3]) : "r"(addr));
}
__device__ __forceinline__ void ldsm_x4_t(uint32_t* r, uint32_t addr) {
    asm volatile("ldmatrix.sync.aligned.m8n8.x4.trans.shared.b16 {%0,%1,%2,%3}, [%4];"
                 : "=r"(r[0]), "=r"(r[1]), "=r"(r[2]), "=r"(r[3]) : "r"(addr));
}
__device__ __forceinline__ void mma_bf16(float* d, const uint32_t* a, const uint32_t* b) {
    asm volatile("mma.sync.aligned.m16n8k16.row.col.f32.bf16.bf16.f32 "
                 "{%0,%1,%2,%3}, {%4,%5,%6,%7}, {%8,%9}, {%0,%1,%2,%3};"
                 : "+f"(d[0]), "+f"(d[1]), "+f"(d[2]), "+f"(d[3])
                 : "r"(a[0]), "r"(a[1]), "r"(a[2]), "r"(a[3]), "r"(b[0]), "r"(b[1]));
}
__device__ __forceinline__ void split_store(const float* __restrict__ in,
                                            __nv_bfloat16* __restrict__ hi,
                                            __nv_bfloat16* __restrict__ lo, int i) {
    float4 v = ((const float4*)in)[i];
    float hx = bf_hi(v.x), hy = bf_hi(v.y), hz = bf_hi(v.z), hw = bf_hi(v.w);
    ((uint2*)hi)[i] = make_uint2(pack_bf16(hx, hy), pack_bf16(hz, hw));
    ((uint2*)lo)[i] = make_uint2(pack_bf16(v.x - hx, v.y - hy), pack_bf16(v.z - hz, v.w - hw));
}
__device__ __forceinline__ int warp_incl_scan(int v, int lane) {
    #pragma unroll
    for (int o = 1; o < 32; o <<= 1) {
        int t = __shfl_up_sync(0xffffffffu, v, o);
        if (lane >= o) v += t;
    }
    return v;
}
__device__ __forceinline__ void fadd4(float4& a, const float4 b) {
    a.x += b.x; a.y += b.y; a.z += b.z; a.w += b.w;
}

// ---------------- K1: degree count + all operand splits (range-dispatched) ----------------
#define CB  ((N_EDGES + 255) / 256)          // 3125 blocks: count degrees
#define XB  ((N_NODES * 32 + 255) / 256)     // 6250 blocks: split x
#define W1B ((128 * 16 + 255) / 256)         // 8 blocks
#define W2B ((64 * 16 + 255) / 256)          // 4 blocks
__global__ void prep_count_kernel(const int* __restrict__ dst, const float* __restrict__ x,
                                  const float* __restrict__ W1, const float* __restrict__ W2) {
    int b = blockIdx.x;
    if (b < CB) {
        int e = b * 256 + threadIdx.x;
        if (e < N_EDGES) atomicAdd(&g_degi[dst[e]], 1);   // degi starts at 0 (invariant)
    } else if (b < CB + XB) {
        int i = (b - CB) * 256 + threadIdx.x;
        if (i < N_NODES * 32) split_store(x, g_xhi, g_xlo, i);
    } else if (b < CB + XB + W1B) {
        int i = (b - CB - XB) * 256 + threadIdx.x;
        if (i < 128 * 16) split_store(W1, g_w1hi, g_w1lo, i);
    } else {
        int i = (b - CB - XB - W1B) * 256 + threadIdx.x;
        if (i < 64 * 16) split_store(W2, g_w2hi, g_w2lo, i);
    }
}

// ---------------- K2: decoupled-lookback scan (+dinv) fused with gemm1 ----------------
#define FLAG_AGG (1u << 30)
#define FLAG_PRE (2u << 30)
#define VAL_MASK 0x3FFFFFFFu

__device__ __forceinline__ void scan_block_body(int b) {
    __shared__ int wsum[8];
    __shared__ int s_base;
    int i = b * 256 + threadIdx.x;
    int lane = threadIdx.x & 31, w = threadIdx.x >> 5;

    int d = (i < N_NODES) ? g_degi[i] : 0;
    if (i < N_NODES) g_dinv[i] = rsqrtf((float)d + 1.0f);   // +1 = self-loop
    int s = warp_incl_scan(d, lane);
    if (lane == 31) wsum[w] = s;
    __syncthreads();
    if (w == 0) {
        int ws = (lane < 8) ? wsum[lane] : 0;
        ws = warp_incl_scan(ws, lane);
        if (lane < 8) wsum[lane] = ws;
    }
    __syncthreads();
    int base = (w > 0) ? wsum[w - 1] : 0;
    int incl = base + s;                 // inclusive within block
    uint32_t blocksum = (uint32_t)wsum[7];

    if (threadIdx.x == 0) {
        if (b == 0) {
            atomicExch(&g_scanstate[0], FLAG_PRE | blocksum);
            s_base = 0;
        } else {
            atomicExch(&g_scanstate[b], FLAG_AGG | blocksum);
        }
    }
    if (b > 0 && w == 0) {               // warp 0 lookback
        uint32_t exc = 0;
        int look = b - 1;
        while (true) {
            int idx = look - lane;
            uint32_t f = 0, val = 0;
            if (idx >= 0) {
                uint32_t v;
                do { v = atomicAdd(&g_scanstate[idx], 0u); } while ((v >> 30) == 0u);
                f = v >> 30;
                val = v & VAL_MASK;
            }
            unsigned pm = __ballot_sync(0xffffffffu, f == 2u);
            if (pm) {
                int cut = __ffs(pm) - 1;
                if (lane > cut) val = 0;
            }
            #pragma unroll
            for (int o = 16; o > 0; o >>= 1) val += __shfl_xor_sync(0xffffffffu, val, o);
            exc += val;
            if (pm) break;
            look -= 32;
        }
        if (lane == 0) {
            s_base = (int)exc;
            atomicExch(&g_scanstate[b], FLAG_PRE | (exc + blocksum));
        }
    }
    __syncthreads();
    if (i < N_NODES) g_rowptr[i] = s_base + incl - d;       // exclusive
    if (i == 0) g_rowptr[N_NODES] = N_EDGES;
    // signal dinv/rowptr complete (gemm epilogues wait on this)
    __syncthreads();
    if (threadIdx.x == 0) {
        __threadfence();
        atomicAdd(&g_scandone, 1);
    }
}

__global__ __launch_bounds__(256)
void scan_gemm1_kernel(const __nv_bfloat16* __restrict__ Ahi, const __nv_bfloat16* __restrict__ Alo,
                       const __nv_bfloat16* __restrict__ Bhi, const __nv_bfloat16* __restrict__ Blo,
                       float* __restrict__ C, int M)
{
    if (blockIdx.x < NSCAN_BLOCKS) { scan_block_body(blockIdx.x); return; }

    constexpr int K = 128;
    constexpr int SA_H = K + 8;
    constexpr int SB_H = 72;
    constexpr int A_HI = 0;
    constexpr int A_LO = 128 * SA_H * 2;
    constexpr int B_HI = 2 * 128 * SA_H * 2;
    constexpr int B_LO = B_HI + K * SB_H * 2;

    extern __shared__ char smem[];
    const uint32_t sbase = smem_u32(smem);
    const int tid  = threadIdx.x;
    const int wid  = tid >> 5;
    const int lane = tid & 31;
    const int row0 = (blockIdx.x - NSCAN_BLOCKS) * 128;

    constexpr int ACH = K / 8;
    #pragma unroll
    for (int idx = tid; idx < 128 * ACH; idx += 256) {
        int r  = idx / ACH;
        int kc = (idx - r * ACH) * 8;
        int row = row0 + r;
        uint32_t sz = (row < M) ? 16u : 0u;
        size_t goff = (size_t)(row < M ? row : 0) * K + kc;
        uint32_t d = sbase + A_HI + (uint32_t)(r * SA_H + kc) * 2;
        cp16(d,                 &Ahi[goff], sz);
        cp16(d + (A_LO - A_HI), &Alo[goff], sz);
    }
    #pragma unroll
    for (int idx = tid; idx < K * 8; idx += 256) {
        int k = idx >> 3, nc = (idx & 7) * 8;
        uint32_t d = sbase + B_HI + (uint32_t)(k * SB_H + nc) * 2;
        cp16(d,                 &Bhi[k * 64 + nc], 16u);
        cp16(d + (B_LO - B_HI), &Blo[k * 64 + nc], 16u);
    }
    cp_commit_wait();
    __syncthreads();

    const int wm = (wid & 3) * 32;
    const int wn = (wid >> 2) * 32;
    const int lrow = lane & 15;
    const int lsel = (lane >> 4) * 8;

    float acc[2][4][4];
    #pragma unroll
    for (int mt = 0; mt < 2; mt++)
        #pragma unroll
        for (int nt = 0; nt < 4; nt++)
            #pragma unroll
            for (int i = 0; i < 4; i++) acc[mt][nt][i] = 0.f;

    #pragma unroll
    for (int k0 = 0; k0 < K; k0 += 16) {
        uint32_t a_hi[2][4], a_lo[2][4];
        #pragma unroll
        for (int mt = 0; mt < 2; mt++) {
            uint32_t off = (uint32_t)((wm + 16 * mt + lrow) * SA_H + k0 + lsel) * 2;
            ldsm_x4(a_hi[mt], sbase + A_HI + off);
            ldsm_x4(a_lo[mt], sbase + A_LO + off);
        }
        uint32_t b_hi[2][4], b_lo[2][4];
        #pragma unroll
        for (int h = 0; h < 2; h++) {
            uint32_t off = (uint32_t)((k0 + lrow) * SB_H + wn + 16 * h + lsel) * 2;
            ldsm_x4_t(b_hi[h], sbase + B_HI + off);
            ldsm_x4_t(b_lo[h], sbase + B_LO + off);
        }
        #pragma unroll
        for (int mt = 0; mt < 2; mt++)
            #pragma unroll
            for (int nt = 0; nt < 4; nt++) {
                const uint32_t* bh = &b_hi[nt >> 1][(nt & 1) * 2];
                const uint32_t* bl = &b_lo[nt >> 1][(nt & 1) * 2];
                mma_bf16(acc[mt][nt], a_hi[mt], bh);
                mma_bf16(acc[mt][nt], a_hi[mt], bl);
                mma_bf16(acc[mt][nt], a_lo[mt], bh);
            }
    }

    // wait for scan blocks (dinv ready); one thread spins, all sync after
    __shared__ int s_ready;
    if (tid == 0) {
        while (atomicAdd(&g_scandone, 0) < NSCAN_BLOCKS) {}
        __threadfence();
        s_ready = 1;
    }
    __syncthreads();

    const int g  = lane >> 2;
    const int tg = lane & 3;
    #pragma unroll
    for (int mt = 0; mt < 2; mt++)
        #pragma unroll
        for (int rh = 0; rh < 2; rh++) {
            int row = row0 + wm + 16 * mt + g + 8 * rh;
            if (row >= M) continue;
            float di = g_dinv[row];
            #pragma unroll
            for (int nt = 0; nt < 4; nt++) {
                int col = wn + 8 * nt + 2 * tg;
                *(float2*)&C[(size_t)row * 64 + col] =
                    make_float2(acc[mt][nt][2 * rh] * di, acc[mt][nt][2 * rh + 1] * di);
            }
        }
}

// ---------------- K3: fill CSR (byte offsets; restores invariants) ----------------
__global__ void fill_csr_kernel(const int* __restrict__ src, const int* __restrict__ dst) {
    int e = blockIdx.x * 256 + threadIdx.x;
    if (blockIdx.x == 0) {
        if (threadIdx.x < NSCAN_BLOCKS) g_scanstate[threadIdx.x] = 0u;
        if (threadIdx.x == 0) g_scandone = 0;
    }
    if (e >= N_EDGES) return;
    int d = dst[e];
    int old = atomicSub(&g_degi[d], 1);      // degi returns to 0 after this kernel
    g_csr[g_rowptr[d] + old - 1] = src[e] << 8;   // byte offset: src*256
}

// ---------------- pre-split mma GEMM (layer 2), epilogue scaled by dinv ----------------
template<int K>
__global__ __launch_bounds__(256)
void mma_gemm_pre(const __nv_bfloat16* __restrict__ Ahi, const __nv_bfloat16* __restrict__ Alo,
                  const __nv_bfloat16* __restrict__ Bhi, const __nv_bfloat16* __restrict__ Blo,
                  float* __restrict__ C, int M)
{
    constexpr int SA_H = K + 8;
    constexpr int SB_H = 72;
    constexpr int A_HI = 0;
    constexpr int A_LO = 128 * SA_H * 2;
    constexpr int B_HI = 2 * 128 * SA_H * 2;
    constexpr int B_LO = B_HI + K * SB_H * 2;

    extern __shared__ char smem[];
    const uint32_t sbase = smem_u32(smem);
    const int tid  = threadIdx.x;
    const int wid  = tid >> 5;
    const int lane = tid & 31;
    const int row0 = blockIdx.x * 128;

    constexpr int ACH = K / 8;
    #pragma unroll
    for (int idx = tid; idx < 128 * ACH; idx += 256) {
        int r  = idx / ACH;
        int kc = (idx - r * ACH) * 8;
        int row = row0 + r;
        uint32_t sz = (row < M) ? 16u : 0u;
        size_t goff = (size_t)(row < M ? row : 0) * K + kc;
        uint32_t d = sbase + A_HI + (uint32_t)(r * SA_H + kc) * 2;
        cp16(d,                 &Ahi[goff], sz);
        cp16(d + (A_LO - A_HI), &Alo[goff], sz);
    }
    #pragma unroll
    for (int idx = tid; idx < K * 8; idx += 256) {
        int k = idx >> 3, nc = (idx & 7) * 8;
        uint32_t d = sbase + B_HI + (uint32_t)(k * SB_H + nc) * 2;
        cp16(d,                 &Bhi[k * 64 + nc], 16u);
        cp16(d + (B_LO - B_HI), &Blo[k * 64 + nc], 16u);
    }
    cp_commit_wait();
    __syncthreads();

    const int wm = (wid & 3) * 32;
    const int wn = (wid >> 2) * 32;
    const int lrow = lane & 15;
    const int lsel = (lane >> 4) * 8;

    float acc[2][4][4];
    #pragma unroll
    for (int mt = 0; mt < 2; mt++)
        #pragma unroll
        for (int nt = 0; nt < 4; nt++)
            #pragma unroll
            for (int i = 0; i < 4; i++) acc[mt][nt][i] = 0.f;

    #pragma unroll
    for (int k0 = 0; k0 < K; k0 += 16) {
        uint32_t a_hi[2][4], a_lo[2][4];
        #pragma unroll
        for (int mt = 0; mt < 2; mt++) {
            uint32_t off = (uint32_t)((wm + 16 * mt + lrow) * SA_H + k0 + lsel) * 2;
            ldsm_x4(a_hi[mt], sbase + A_HI + off);
            ldsm_x4(a_lo[mt], sbase + A_LO + off);
        }
        uint32_t b_hi[2][4], b_lo[2][4];
        #pragma unroll
        for (int h = 0; h < 2; h++) {
            uint32_t off = (uint32_t)((k0 + lrow) * SB_H + wn + 16 * h + lsel) * 2;
            ldsm_x4_t(b_hi[h], sbase + B_HI + off);
            ldsm_x4_t(b_lo[h], sbase + B_LO + off);
        }
        #pragma unroll
        for (int mt = 0; mt < 2; mt++)
            #pragma unroll
            for (int nt = 0; nt < 4; nt++) {
                const uint32_t* bh = &b_hi[nt >> 1][(nt & 1) * 2];
                const uint32_t* bl = &b_lo[nt >> 1][(nt & 1) * 2];
                mma_bf16(acc[mt][nt], a_hi[mt], bh);
                mma_bf16(acc[mt][nt], a_hi[mt], bl);
                mma_bf16(acc[mt][nt], a_lo[mt], bh);
            }
    }

    const int g  = lane >> 2;
    const int tg = lane & 3;
    #pragma unroll
    for (int mt = 0; mt < 2; mt++)
        #pragma unroll
        for (int rh = 0; rh < 2; rh++) {
            int row = row0 + wm + 16 * mt + g + 8 * rh;
            if (row >= M) continue;
            float di = g_dinv[row];
            #pragma unroll
            for (int nt = 0; nt < 4; nt++) {
                int col = wn + 8 * nt + 2 * tg;
                *(float2*)&C[(size_t)row * 64 + col] =
                    make_float2(acc[mt][nt][2 * rh] * di, acc[mt][nt][2 * rh + 1] * di);
            }
        }
}

// ---------------- CSR gather: half-warp float4 lanes, 2 edges per LDG.128 ----------------
// out = dd*(Σ h'[s] + h'[node]),  h' pre-scaled by dinv[row]
template<bool LAYER1>
__global__ __launch_bounds__(256)
void gather_kernel(const float* __restrict__ h, const float* __restrict__ bias,
                   float* __restrict__ zout)
{
    int node = blockIdx.x * 8 + (threadIdx.x >> 5);   // warp per node
    int lane = threadIdx.x & 31;
    if (node >= N_NODES) return;
    const int half = lane >> 4;         // 0/1: which edge of a pair
    const int q    = lane & 15;         // float4 slot within 256B row

    const char* hp = (const char*)h + q * 16;

    float4 a0, a1 = make_float4(0.f, 0.f, 0.f, 0.f);
    if (half == 0) a0 = *(const float4*)(hp + (size_t)node * 256);   // self-loop
    else           a0 = make_float4(0.f, 0.f, 0.f, 0.f);

    int e   = __ldg(&g_rowptr[node]);
    int end = __ldg(&g_rowptr[node + 1]);

    if ((e & 1) && e < end) {           // odd head -> align e to 2
        if (half == 0) {
            int o = __ldg(&g_csr[e]);
            fadd4(a1, *(const float4*)(hp + o));
        }
        e++;
    }
    for (; e + 3 < end; e += 4) {       // 4 edges: 2 uniform int2 + 2 LDG.128/lane
        int2 oA = *(const int2*)&g_csr[e];
        int2 oB = *(const int2*)&g_csr[e + 2];
        float4 va = *(const float4*)(hp + (half ? oA.y : oA.x));
        float4 vb = *(const float4*)(hp + (half ? oB.y : oB.x));
        fadd4(a0, va);
        fadd4(a1, vb);
    }
    if (e + 1 < end) {                  // 2-edge tail
        int2 o = *(const int2*)&g_csr[e];
        fadd4(a0, *(const float4*)(hp + (half ? o.y : o.x)));
        e += 2;
    }
    if (e < end && half == 0) {         // final single edge
        int o = __ldg(&g_csr[e]);
        fadd4(a1, *(const float4*)(hp + o));
    }

    fadd4(a0, a1);
    // combine halves: lanes l and l+16 hold the same 4 columns
    a0.x += __shfl_xor_sync(0xffffffffu, a0.x, 16);
    a0.y += __shfl_xor_sync(0xffffffffu, a0.y, 16);
    a0.z += __shfl_xor_sync(0xffffffffu, a0.z, 16);
    a0.w += __shfl_xor_sync(0xffffffffu, a0.w, 16);

    if (half != 0) return;
    float dd = g_dinv[node];
    a0.x *= dd; a0.y *= dd; a0.z *= dd; a0.w *= dd;

    if (LAYER1) {
        float4 b = *(const float4*)&bias[q * 4];
        float vx = fmaxf(a0.x + b.x, 0.f);
        float vy = fmaxf(a0.y + b.y, 0.f);
        float vz = fmaxf(a0.z + b.z, 0.f);
        float vw = fmaxf(a0.w + b.w, 0.f);
        float hx = bf_hi(vx), hy = bf_hi(vy), hz = bf_hi(vz), hw = bf_hi(vw);
        uint32_t* zh = (uint32_t*)g_z1hi + node * 32 + q * 2;
        uint32_t* zl = (uint32_t*)g_z1lo + node * 32 + q * 2;
        zh[0] = pack_bf16(hx, hy);       zh[1] = pack_bf16(hz, hw);
        zl[0] = pack_bf16(vx - hx, vy - hy); zl[1] = pack_bf16(vz - hz, vw - hw);
    } else {
        *(float4*)&zout[(size_t)node * 64 + q * 4] = a0;
    }
}

// ---------------- fused decode: ef -> P1+relu -> P2+relu -> P3 dot ----------------
__global__ __launch_bounds__(256)
void decode_kernel(const int* __restrict__ eli, const float* __restrict__ b2,
                   const float* __restrict__ P1, const float* __restrict__ pb1,
                   const float* __restrict__ P2, const float* __restrict__ pb2,
                   const float* __restrict__ P3, const float* __restrict__ pb3,
                   float* __restrict__ out)
{
    constexpr int SA_H = 72, SB_H = 72;
    constexpr int EF_HI = 0;
    constexpr int EF_LO = 128 * SA_H * 2;
    constexpr int P1_HI = 2 * 128 * SA_H * 2;
    constexpr int P1_LO = P1_HI + 64 * SB_H * 2;
    constexpr int P2_HI = P1_LO + 64 * SB_H * 2;
    constexpr int P2_LO = P2_HI + 64 * SB_H * 2;
    constexpr int S_OUT = P2_LO + 64 * SB_H * 2;

    extern __shared__ char smem[];
    const uint32_t sbase = smem_u32(smem);
    const int tid  = threadIdx.x;
    const int wid  = tid >> 5;
    const int lane = tid & 31;
    const int row0 = blockIdx.x * 128;

    if (tid < 128) *(float*)(smem + S_OUT + tid * 4) = 0.f;

    #pragma unroll
    for (int idx = tid; idx < 128 * 16; idx += 256) {
        int pl = idx >> 4, c4 = (idx & 15) << 2;
        int p = row0 + pl;
        float4 r = make_float4(0.f, 0.f, 0.f, 0.f);
        if (p < N_EL) {
            int a = __ldg(&eli[p]);
            int b = __ldg(&eli[N_EL + p]);
            float4 bb = *(const float4*)&b2[c4];
            float4 za = *(const float4*)&g_z2[a * 64 + c4];
            float4 zb = *(const float4*)&g_z2[b * 64 + c4];
            r.x = (za.x + bb.x) * (zb.x + bb.x);
            r.y = (za.y + bb.y) * (zb.y + bb.y);
            r.z = (za.z + bb.z) * (zb.z + bb.z);
            r.w = (za.w + bb.w) * (zb.w + bb.w);
        }
        float hx = bf_hi(r.x), hy = bf_hi(r.y), hz = bf_hi(r.z), hw = bf_hi(r.w);
        uint32_t off = (uint32_t)(pl * SA_H + c4) * 2;
        *(uint2*)(smem + EF_HI + off) = make_uint2(pack_bf16(hx, hy), pack_bf16(hz, hw));
        *(uint2*)(smem + EF_LO + off) = make_uint2(pack_bf16(r.x - hx, r.y - hy),
                                                   pack_bf16(r.z - hz, r.w - hw));
    }
    #pragma unroll
    for (int idx = tid; idx < 64 * 16; idx += 256) {
        int k = idx >> 4, nc = (idx & 15) << 2;
        uint32_t off = (uint32_t)(k * SB_H + nc) * 2;
        float4 v = *(const float4*)&P1[k * 64 + nc];
        float hx = bf_hi(v.x), hy = bf_hi(v.y), hz = bf_hi(v.z), hw = bf_hi(v.w);
        *(uint2*)(smem + P1_HI + off) = make_uint2(pack_bf16(hx, hy), pack_bf16(hz, hw));
        *(uint2*)(smem + P1_LO + off) = make_uint2(pack_bf16(v.x - hx, v.y - hy),
                                                   pack_bf16(v.z - hz, v.w - hw));
        float4 u = *(const float4*)&P2[k * 64 + nc];
        float ux = bf_hi(u.x), uy = bf_hi(u.y), uz = bf_hi(u.z), uw = bf_hi(u.w);
        *(uint2*)(smem + P2_HI + off) = make_uint2(pack_bf16(ux, uy), pack_bf16(uz, uw));
        *(uint2*)(smem + P2_LO + off) = make_uint2(pack_bf16(u.x - ux, u.y - uy),
                                                   pack_bf16(u.z - uz, u.w - uw));
    }
    __syncthreads();

    const int wm = (wid & 3) * 32;
    const int wn = (wid >> 2) * 32;
    const int lrow = lane & 15;
    const int lsel = (lane >> 4) * 8;
    const int g  = lane >> 2;
    const int tg = lane & 3;

    float acc[2][4][4];
    #pragma unroll
    for (int mt = 0; mt < 2; mt++)
        #pragma unroll
        for (int nt = 0; nt < 4; nt++)
            #pragma unroll
            for (int i = 0; i < 4; i++) acc[mt][nt][i] = 0.f;

    #pragma unroll
    for (int k0 = 0; k0 < 64; k0 += 16) {
        uint32_t a_hi[2][4], a_lo[2][4];
        #pragma unroll
        for (int mt = 0; mt < 2; mt++) {
            uint32_t off = (uint32_t)((wm + 16 * mt + lrow) * SA_H + k0 + lsel) * 2;
            ldsm_x4(a_hi[mt], sbase + EF_HI + off);
            ldsm_x4(a_lo[mt], sbase + EF_LO + off);
        }
        uint32_t b_hi[2][4], b_lo[2][4];
        #pragma unroll
        for (int h = 0; h < 2; h++) {
            uint32_t off = (uint32_t)((k0 + lrow) * SB_H + wn + 16 * h + lsel) * 2;
            ldsm_x4_t(b_hi[h], sbase + P1_HI + off);
            ldsm_x4_t(b_lo[h], sbase + P1_LO + off);
        }
        #pragma unroll
        for (int mt = 0; mt < 2; mt++)
            #pragma unroll
            for (int nt = 0; nt < 4; nt++) {
                const uint32_t* bh = &b_hi[nt >> 1][(nt & 1) * 2];
                const uint32_t* bl = &b_lo[nt >> 1][(nt & 1) * 2];
                mma_bf16(acc[mt][nt], a_hi[mt], bh);
                mma_bf16(acc[mt][nt], a_hi[mt], bl);
                mma_bf16(acc[mt][nt], a_lo[mt], bh);
            }
    }
    __syncthreads();

    #pragma unroll
    for (int mt = 0; mt < 2; mt++)
        #pragma unroll
        for (int rh = 0; rh < 2; rh++) {
            int rl = wm + 16 * mt + g + 8 * rh;
            #pragma unroll
            for (int nt = 0; nt < 4; nt++) {
                int col = wn + 8 * nt + 2 * tg;
                float vx = fmaxf(acc[mt][nt][2 * rh]     + __ldg(&pb1[col]),     0.f);
                float vy = fmaxf(acc[mt][nt][2 * rh + 1] + __ldg(&pb1[col + 1]), 0.f);
                float hx = bf_hi(vx), hy = bf_hi(vy);
                uint32_t off = (uint32_t)(rl * SA_H + col) * 2;
                *(uint32_t*)(smem + EF_HI + off) = pack_bf16(hx, hy);
                *(uint32_t*)(smem + EF_LO + off) = pack_bf16(vx - hx, vy - hy);
            }
        }
    __syncthreads();

    #pragma unroll
    for (int mt = 0; mt < 2; mt++)
        #pragma unroll
        for (int nt = 0; nt < 4; nt++)
            #pragma unroll
            for (int i = 0; i < 4; i++) acc[mt][nt][i] = 0.f;

    #pragma unroll
    for (int k0 = 0; k0 < 64; k0 += 16) {
        uint32_t a_hi[2][4], a_lo[2][4];
        #pragma unroll
        for (int mt = 0; mt < 2; mt++) {
            uint32_t off = (uint32_t)((wm + 16 * mt + lrow) * SA_H + k0 + lsel) * 2;
            ldsm_x4(a_hi[mt], sbase + EF_HI + off);
            ldsm_x4(a_lo[mt], sbase + EF_LO + off);
        }
        uint32_t b_hi[2][4], b_lo[2][4];
        #pragma unroll
        for (int h = 0; h < 2; h++) {
            uint32_t off = (uint32_t)((k0 + lrow) * SB_H + wn + 16 * h + lsel) * 2;
            ldsm_x4_t(b_hi[h], sbase + P2_HI + off);
            ldsm_x4_t(b_lo[h], sbase + P2_LO + off);
        }
        #pragma unroll
        for (int mt = 0; mt < 2; mt++)
            #pragma unroll
            for (int nt = 0; nt < 4; nt++) {
                const uint32_t* bh = &b_hi[nt >> 1][(nt & 1) * 2];
                const uint32_t* bl = &b_lo[nt >> 1][(nt & 1) * 2];
                mma_bf16(acc[mt][nt], a_hi[mt], bh);
                mma_bf16(acc[mt][nt], a_hi[mt], bl);
                mma_bf16(acc[mt][nt], a_lo[mt], bh);
            }
    }

    #pragma unroll
    for (int mt = 0; mt < 2; mt++)
        #pragma unroll
        for (int rh = 0; rh < 2; rh++) {
            float s = 0.f;
            #pragma unroll
            for (int nt = 0; nt < 4; nt++) {
                int col = wn + 8 * nt + 2 * tg;
                float vx = fmaxf(acc[mt][nt][2 * rh]     + __ldg(&pb2[col]),     0.f);
                float vy = fmaxf(acc[mt][nt][2 * rh + 1] + __ldg(&pb2[col + 1]), 0.f);
                s += vx * __ldg(&P3[col]) + vy * __ldg(&P3[col + 1]);
            }
            s += __shfl_xor_sync(0xffffffffu, s, 1);
            s += __shfl_xor_sync(0xffffffffu, s, 2);
            if (tg == 0) {
                int rl = wm + 16 * mt + g + 8 * rh;
                atomicAdd((float*)(smem + S_OUT) + rl, s);
            }
        }
    __syncthreads();
    if (tid < 128) {
        int p = row0 + tid;
        if (p < N_EL) out[p] = *(float*)(smem + S_OUT + tid * 4) + __ldg(&pb3[0]);
    }
}

// ---------------- launcher ----------------
extern "C" void kernel_launch(void* const* d_in, const int* in_sizes, int n_in,
                              void* d_out, int out_size)
{
    const float* x   = (const float*)d_in[0];
    const int*   ei  = (const int*)  d_in[1];
    const int*   eli = (const int*)  d_in[2];
    const float* W1  = (const float*)d_in[3];
    const float* b1  = (const float*)d_in[4];
    const float* W2  = (const float*)d_in[5];
    const float* b2  = (const float*)d_in[6];
    const float* P1  = (const float*)d_in[7];
    const float* pb1 = (const float*)d_in[8];
    const float* P2  = (const float*)d_in[9];
    const float* pb2 = (const float*)d_in[10];
    const float* P3  = (const float*)d_in[11];
    const float* pb3 = (const float*)d_in[12];
    float* out = (float*)d_out;

    const int* src = ei;
    const int* dst = ei + N_EDGES;

    float *ph1, *ph2, *pz2;
    cudaGetSymbolAddress((void**)&ph1, g_h1);
    cudaGetSymbolAddress((void**)&ph2, g_h2);
    cudaGetSymbolAddress((void**)&pz2, g_z2);
    __nv_bfloat16 *pxhi, *pxlo, *pz1hi, *pz1lo, *pw1hi, *pw1lo, *pw2hi, *pw2lo;
    cudaGetSymbolAddress((void**)&pxhi,  g_xhi);
    cudaGetSymbolAddress((void**)&pxlo,  g_xlo);
    cudaGetSymbolAddress((void**)&pz1hi, g_z1hi);
    cudaGetSymbolAddress((void**)&pz1lo, g_z1lo);
    cudaGetSymbolAddress((void**)&pw1hi, g_w1hi);
    cudaGetSymbolAddress((void**)&pw1lo, g_w1lo);
    cudaGetSymbolAddress((void**)&pw2hi, g_w2hi);
    cudaGetSymbolAddress((void**)&pw2lo, g_w2lo);

    const int SM128 = 2 * 128 * (128 + 8) * 2 + 2 * 128 * 72 * 2;  // 106496
    const int SM64  = 2 * 128 * (64 + 8) * 2  + 2 * 64 * 72 * 2;   //  55296
    const int SMDEC = 2 * 128 * 72 * 2 + 6 * 64 * 72 * 2 + 512;    //  74240
    cudaFuncSetAttribute(scan_gemm1_kernel, cudaFuncAttributeMaxDynamicSharedMemorySize, SM128);
    cudaFuncSetAttribute(mma_gemm_pre<64>,  cudaFuncAttributeMaxDynamicSharedMemorySize, SM64);
    cudaFuncSetAttribute(decode_kernel,     cudaFuncAttributeMaxDynamicSharedMemorySize, SMDEC);

    const int gbN  = (N_NODES + 127) / 128;   // 391
    const int gbEL = (N_EL    + 127) / 128;   // 782
    const int gbG  = (N_NODES + 7) / 8;       // 6250

    // K1: degree count + operand splits (degi starts at 0 by invariant)
    prep_count_kernel<<<CB + XB + W1B + W2B, 256>>>(dst, x, W1, W2);
    // K2: lookback scan (+dinv) fused with gemm1; epilogue scales by dinv after scan-done
    scan_gemm1_kernel<<<NSCAN_BLOCKS + gbN, 256, SM128>>>(pxhi, pxlo, pw1hi, pw1lo, ph1, N_NODES);
    // K3: CSR fill (byte offsets; restores degi=0, scanstate=0, scandone=0)
    fill_csr_kernel<<<CB, 256>>>(src, dst);
    // gather layer 1 (+bias+relu+split fused)
    gather_kernel<true><<<gbG, 256>>>(ph1, b1, nullptr);
    // conv layer 2 (epilogue scaled by dinv)
    mma_gemm_pre<64><<<gbN, 256, SM64>>>(pz1hi, pz1lo, pw2hi, pw2lo, ph2, N_NODES);
    gather_kernel<false><<<gbG, 256>>>(ph2, nullptr, pz2);
    // fused decode
    decode_kernel<<<gbEL, 256, SMDEC>>>(eli, b2, P1, pb1, P2, pb2, P3, pb3, out);
}

// round 12
// speedup vs baseline: 1.4656x; 1.4656x over previous
#include <cuda_runtime.h>
#include <cuda_bf16.h>
#include <cstdint>

#define N_NODES 50000
#define N_EDGES 800000
#define N_EL    100000
#define NSCAN_BLOCKS ((N_NODES + 255) / 256)   // 196

// ---------------- scratch (device globals; no allocation allowed) ----------------
// INVARIANT: g_degi, g_scanstate, g_scandone are zero at the start of every run.
// (zero-initialized at module load; fill_csr_kernel restores them each run)
__device__ int      g_degi     [N_NODES];
__device__ uint32_t g_scanstate[NSCAN_BLOCKS];
__device__ int      g_scandone;
__device__ int      g_rowptr   [N_NODES + 1];
__device__ int      g_csr      [N_EDGES];      // BYTE offsets: src*256
__device__ float g_dinv[N_NODES];
__device__ float g_h1  [N_NODES * 64];         // scaled: h1*dinv[row]
__device__ float g_h2  [N_NODES * 64];         // scaled: h2*dinv[row]
__device__ float g_z2  [N_NODES * 64];
// pre-split bf16 operand arrays
__device__ __nv_bfloat16 g_xhi [N_NODES * 128];
__device__ __nv_bfloat16 g_xlo [N_NODES * 128];
__device__ __nv_bfloat16 g_z1hi[N_NODES * 64];
__device__ __nv_bfloat16 g_z1lo[N_NODES * 64];
__device__ __nv_bfloat16 g_w1hi[128 * 64];
__device__ __nv_bfloat16 g_w1lo[128 * 64];
__device__ __nv_bfloat16 g_w2hi[64 * 64];
__device__ __nv_bfloat16 g_w2lo[64 * 64];

// ---------------- helpers ----------------
__device__ __forceinline__ uint32_t smem_u32(const void* p) {
    uint32_t a;
    asm("{ .reg .u64 t; cvta.to.shared.u64 t, %1; cvt.u32.u64 %0, t; }" : "=r"(a) : "l"(p));
    return a;
}
__device__ __forceinline__ uint32_t pack_bf16(float x, float y) {
    __nv_bfloat162 t = __floats2bfloat162_rn(x, y);
    return *(uint32_t*)&t;
}
__device__ __forceinline__ float bf_hi(float x) {
    return __bfloat162float(__float2bfloat16_rn(x));
}
__device__ __forceinline__ void cp16(uint32_t dst, const void* src, uint32_t sz) {
    asm volatile("cp.async.ca.shared.global [%0], [%1], 16, %2;"
                 :: "r"(dst), "l"(src), "r"(sz) : "memory");
}
__device__ __forceinline__ void cp_commit_wait() {
    asm volatile("cp.async.commit_group;");
    asm volatile("cp.async.wait_group 0;" ::: "memory");
}
__device__ __forceinline__ void ldsm_x4(uint32_t* r, uint32_t addr) {
    asm volatile("ldmatrix.sync.aligned.m8n8.x4.shared.b16 {%0,%1,%2,%3}, [%4];"
                 : "=r"(r[0]), "=r"(r[1]), "=r"(r[2]), "=r"(r[3]) : "r"(addr));
}
__device__ __forceinline__ void ldsm_x4_t(uint32_t* r, uint32_t addr) {
    asm volatile("ldmatrix.sync.aligned.m8n8.x4.trans.shared.b16 {%0,%1,%2,%3}, [%4];"
                 : "=r"(r[0]), "=r"(r[1]), "=r"(r[2]), "=r"(r[3]) : "r"(addr));
}
__device__ __forceinline__ void mma_bf16(float* d, const uint32_t* a, const uint32_t* b) {
    asm volatile("mma.sync.aligned.m16n8k16.row.col.f32.bf16.bf16.f32 "
                 "{%0,%1,%2,%3}, {%4,%5,%6,%7}, {%8,%9}, {%0,%1,%2,%3};"
                 : "+f"(d[0]), "+f"(d[1]), "+f"(d[2]), "+f"(d[3])
                 : "r"(a[0]), "r"(a[1]), "r"(a[2]), "r"(a[3]), "r"(b[0]), "r"(b[1]));
}
__device__ __forceinline__ void split_store(const float* __restrict__ in,
                                            __nv_bfloat16* __restrict__ hi,
                                            __nv_bfloat16* __restrict__ lo, int i) {
    float4 v = ((const float4*)in)[i];
    float hx = bf_hi(v.x), hy = bf_hi(v.y), hz = bf_hi(v.z), hw = bf_hi(v.w);
    ((uint2*)hi)[i] = make_uint2(pack_bf16(hx, hy), pack_bf16(hz, hw));
    ((uint2*)lo)[i] = make_uint2(pack_bf16(v.x - hx, v.y - hy), pack_bf16(v.z - hz, v.w - hw));
}
__device__ __forceinline__ int warp_incl_scan(int v, int lane) {
    #pragma unroll
    for (int o = 1; o < 32; o <<= 1) {
        int t = __shfl_up_sync(0xffffffffu, v, o);
        if (lane >= o) v += t;
    }
    return v;
}

// ---------------- K1: degree count + all operand splits (range-dispatched) ----------------
#define CB  ((N_EDGES + 255) / 256)          // 3125 blocks: count degrees
#define XB  ((N_NODES * 32 + 255) / 256)     // 6250 blocks: split x
#define W1B ((128 * 16 + 255) / 256)         // 8 blocks
#define W2B ((64 * 16 + 255) / 256)          // 4 blocks
__global__ void prep_count_kernel(const int* __restrict__ dst, const float* __restrict__ x,
                                  const float* __restrict__ W1, const float* __restrict__ W2) {
    int b = blockIdx.x;
    if (b < CB) {
        int e = b * 256 + threadIdx.x;
        if (e < N_EDGES) atomicAdd(&g_degi[dst[e]], 1);   // degi starts at 0 (invariant)
    } else if (b < CB + XB) {
        int i = (b - CB) * 256 + threadIdx.x;
        if (i < N_NODES * 32) split_store(x, g_xhi, g_xlo, i);
    } else if (b < CB + XB + W1B) {
        int i = (b - CB - XB) * 256 + threadIdx.x;
        if (i < 128 * 16) split_store(W1, g_w1hi, g_w1lo, i);
    } else {
        int i = (b - CB - XB - W1B) * 256 + threadIdx.x;
        if (i < 64 * 16) split_store(W2, g_w2hi, g_w2lo, i);
    }
}

// ---------------- K2: decoupled-lookback scan (+dinv) fused with gemm1 ----------------
#define FLAG_AGG (1u << 30)
#define FLAG_PRE (2u << 30)
#define VAL_MASK 0x3FFFFFFFu

__device__ __forceinline__ void scan_block_body(int b) {
    __shared__ int wsum[8];
    __shared__ int s_base;
    int i = b * 256 + threadIdx.x;
    int lane = threadIdx.x & 31, w = threadIdx.x >> 5;

    int d = (i < N_NODES) ? g_degi[i] : 0;
    if (i < N_NODES) g_dinv[i] = rsqrtf((float)d + 1.0f);   // +1 = self-loop
    int s = warp_incl_scan(d, lane);
    if (lane == 31) wsum[w] = s;
    __syncthreads();
    if (w == 0) {
        int ws = (lane < 8) ? wsum[lane] : 0;
        ws = warp_incl_scan(ws, lane);
        if (lane < 8) wsum[lane] = ws;
    }
    __syncthreads();
    int base = (w > 0) ? wsum[w - 1] : 0;
    int incl = base + s;                 // inclusive within block
    uint32_t blocksum = (uint32_t)wsum[7];

    if (threadIdx.x == 0) {
        if (b == 0) {
            atomicExch(&g_scanstate[0], FLAG_PRE | blocksum);
            s_base = 0;
        } else {
            atomicExch(&g_scanstate[b], FLAG_AGG | blocksum);
        }
    }
    if (b > 0 && w == 0) {               // warp 0 lookback
        uint32_t exc = 0;
        int look = b - 1;
        while (true) {
            int idx = look - lane;
            uint32_t f = 0, val = 0;
            if (idx >= 0) {
                uint32_t v;
                do { v = atomicAdd(&g_scanstate[idx], 0u); } while ((v >> 30) == 0u);
                f = v >> 30;
                val = v & VAL_MASK;
            }
            unsigned pm = __ballot_sync(0xffffffffu, f == 2u);
            if (pm) {
                int cut = __ffs(pm) - 1;
                if (lane > cut) val = 0;
            }
            #pragma unroll
            for (int o = 16; o > 0; o >>= 1) val += __shfl_xor_sync(0xffffffffu, val, o);
            exc += val;
            if (pm) break;
            look -= 32;
        }
        if (lane == 0) {
            s_base = (int)exc;
            atomicExch(&g_scanstate[b], FLAG_PRE | (exc + blocksum));
        }
    }
    __syncthreads();
    if (i < N_NODES) g_rowptr[i] = s_base + incl - d;       // exclusive
    if (i == 0) g_rowptr[N_NODES] = N_EDGES;
    // signal dinv/rowptr complete (gemm epilogues wait on this)
    __syncthreads();
    if (threadIdx.x == 0) {
        __threadfence();
        atomicAdd(&g_scandone, 1);
    }
}

__global__ __launch_bounds__(256)
void scan_gemm1_kernel(const __nv_bfloat16* __restrict__ Ahi, const __nv_bfloat16* __restrict__ Alo,
                       const __nv_bfloat16* __restrict__ Bhi, const __nv_bfloat16* __restrict__ Blo,
                       float* __restrict__ C, int M)
{
    if (blockIdx.x < NSCAN_BLOCKS) { scan_block_body(blockIdx.x); return; }

    constexpr int K = 128;
    constexpr int SA_H = K + 8;
    constexpr int SB_H = 72;
    constexpr int A_HI = 0;
    constexpr int A_LO = 128 * SA_H * 2;
    constexpr int B_HI = 2 * 128 * SA_H * 2;
    constexpr int B_LO = B_HI + K * SB_H * 2;

    extern __shared__ char smem[];
    const uint32_t sbase = smem_u32(smem);
    const int tid  = threadIdx.x;
    const int wid  = tid >> 5;
    const int lane = tid & 31;
    const int row0 = (blockIdx.x - NSCAN_BLOCKS) * 128;

    constexpr int ACH = K / 8;
    #pragma unroll
    for (int idx = tid; idx < 128 * ACH; idx += 256) {
        int r  = idx / ACH;
        int kc = (idx - r * ACH) * 8;
        int row = row0 + r;
        uint32_t sz = (row < M) ? 16u : 0u;
        size_t goff = (size_t)(row < M ? row : 0) * K + kc;
        uint32_t d = sbase + A_HI + (uint32_t)(r * SA_H + kc) * 2;
        cp16(d,                 &Ahi[goff], sz);
        cp16(d + (A_LO - A_HI), &Alo[goff], sz);
    }
    #pragma unroll
    for (int idx = tid; idx < K * 8; idx += 256) {
        int k = idx >> 3, nc = (idx & 7) * 8;
        uint32_t d = sbase + B_HI + (uint32_t)(k * SB_H + nc) * 2;
        cp16(d,                 &Bhi[k * 64 + nc], 16u);
        cp16(d + (B_LO - B_HI), &Blo[k * 64 + nc], 16u);
    }
    cp_commit_wait();
    __syncthreads();

    const int wm = (wid & 3) * 32;
    const int wn = (wid >> 2) * 32;
    const int lrow = lane & 15;
    const int lsel = (lane >> 4) * 8;

    float acc[2][4][4];
    #pragma unroll
    for (int mt = 0; mt < 2; mt++)
        #pragma unroll
        for (int nt = 0; nt < 4; nt++)
            #pragma unroll
            for (int i = 0; i < 4; i++) acc[mt][nt][i] = 0.f;

    #pragma unroll
    for (int k0 = 0; k0 < K; k0 += 16) {
        uint32_t a_hi[2][4], a_lo[2][4];
        #pragma unroll
        for (int mt = 0; mt < 2; mt++) {
            uint32_t off = (uint32_t)((wm + 16 * mt + lrow) * SA_H + k0 + lsel) * 2;
            ldsm_x4(a_hi[mt], sbase + A_HI + off);
            ldsm_x4(a_lo[mt], sbase + A_LO + off);
        }
        uint32_t b_hi[2][4], b_lo[2][4];
        #pragma unroll
        for (int h = 0; h < 2; h++) {
            uint32_t off = (uint32_t)((k0 + lrow) * SB_H + wn + 16 * h + lsel) * 2;
            ldsm_x4_t(b_hi[h], sbase + B_HI + off);
            ldsm_x4_t(b_lo[h], sbase + B_LO + off);
        }
        #pragma unroll
        for (int mt = 0; mt < 2; mt++)
            #pragma unroll
            for (int nt = 0; nt < 4; nt++) {
                const uint32_t* bh = &b_hi[nt >> 1][(nt & 1) * 2];
                const uint32_t* bl = &b_lo[nt >> 1][(nt & 1) * 2];
                mma_bf16(acc[mt][nt], a_hi[mt], bh);
                mma_bf16(acc[mt][nt], a_hi[mt], bl);
                mma_bf16(acc[mt][nt], a_lo[mt], bh);
            }
    }

    // wait for scan blocks (dinv ready); one thread spins, all sync after
    __shared__ int s_ready;
    if (tid == 0) {
        while (atomicAdd(&g_scandone, 0) < NSCAN_BLOCKS) {}
        __threadfence();
        s_ready = 1;
    }
    __syncthreads();

    const int g  = lane >> 2;
    const int tg = lane & 3;
    #pragma unroll
    for (int mt = 0; mt < 2; mt++)
        #pragma unroll
        for (int rh = 0; rh < 2; rh++) {
            int row = row0 + wm + 16 * mt + g + 8 * rh;
            if (row >= M) continue;
            float di = g_dinv[row];
            #pragma unroll
            for (int nt = 0; nt < 4; nt++) {
                int col = wn + 8 * nt + 2 * tg;
                *(float2*)&C[(size_t)row * 64 + col] =
                    make_float2(acc[mt][nt][2 * rh] * di, acc[mt][nt][2 * rh + 1] * di);
            }
        }
}

// ---------------- K3: fill CSR (byte offsets; restores invariants) ----------------
__global__ void fill_csr_kernel(const int* __restrict__ src, const int* __restrict__ dst) {
    int e = blockIdx.x * 256 + threadIdx.x;
    if (blockIdx.x == 0) {
        if (threadIdx.x < NSCAN_BLOCKS) g_scanstate[threadIdx.x] = 0u;
        if (threadIdx.x == 0) g_scandone = 0;
    }
    if (e >= N_EDGES) return;
    int d = dst[e];
    int old = atomicSub(&g_degi[d], 1);      // degi returns to 0 after this kernel
    g_csr[g_rowptr[d] + old - 1] = src[e] << 8;   // byte offset: src*256
}

// ---------------- pre-split mma GEMM (layer 2), epilogue scaled by dinv ----------------
template<int K>
__global__ __launch_bounds__(256)
void mma_gemm_pre(const __nv_bfloat16* __restrict__ Ahi, const __nv_bfloat16* __restrict__ Alo,
                  const __nv_bfloat16* __restrict__ Bhi, const __nv_bfloat16* __restrict__ Blo,
                  float* __restrict__ C, int M)
{
    constexpr int SA_H = K + 8;
    constexpr int SB_H = 72;
    constexpr int A_HI = 0;
    constexpr int A_LO = 128 * SA_H * 2;
    constexpr int B_HI = 2 * 128 * SA_H * 2;
    constexpr int B_LO = B_HI + K * SB_H * 2;

    extern __shared__ char smem[];
    const uint32_t sbase = smem_u32(smem);
    const int tid  = threadIdx.x;
    const int wid  = tid >> 5;
    const int lane = tid & 31;
    const int row0 = blockIdx.x * 128;

    constexpr int ACH = K / 8;
    #pragma unroll
    for (int idx = tid; idx < 128 * ACH; idx += 256) {
        int r  = idx / ACH;
        int kc = (idx - r * ACH) * 8;
        int row = row0 + r;
        uint32_t sz = (row < M) ? 16u : 0u;
        size_t goff = (size_t)(row < M ? row : 0) * K + kc;
        uint32_t d = sbase + A_HI + (uint32_t)(r * SA_H + kc) * 2;
        cp16(d,                 &Ahi[goff], sz);
        cp16(d + (A_LO - A_HI), &Alo[goff], sz);
    }
    #pragma unroll
    for (int idx = tid; idx < K * 8; idx += 256) {
        int k = idx >> 3, nc = (idx & 7) * 8;
        uint32_t d = sbase + B_HI + (uint32_t)(k * SB_H + nc) * 2;
        cp16(d,                 &Bhi[k * 64 + nc], 16u);
        cp16(d + (B_LO - B_HI), &Blo[k * 64 + nc], 16u);
    }
    cp_commit_wait();
    __syncthreads();

    const int wm = (wid & 3) * 32;
    const int wn = (wid >> 2) * 32;
    const int lrow = lane & 15;
    const int lsel = (lane >> 4) * 8;

    float acc[2][4][4];
    #pragma unroll
    for (int mt = 0; mt < 2; mt++)
        #pragma unroll
        for (int nt = 0; nt < 4; nt++)
            #pragma unroll
            for (int i = 0; i < 4; i++) acc[mt][nt][i] = 0.f;

    #pragma unroll
    for (int k0 = 0; k0 < K; k0 += 16) {
        uint32_t a_hi[2][4], a_lo[2][4];
        #pragma unroll
        for (int mt = 0; mt < 2; mt++) {
            uint32_t off = (uint32_t)((wm + 16 * mt + lrow) * SA_H + k0 + lsel) * 2;
            ldsm_x4(a_hi[mt], sbase + A_HI + off);
            ldsm_x4(a_lo[mt], sbase + A_LO + off);
        }
        uint32_t b_hi[2][4], b_lo[2][4];
        #pragma unroll
        for (int h = 0; h < 2; h++) {
            uint32_t off = (uint32_t)((k0 + lrow) * SB_H + wn + 16 * h + lsel) * 2;
            ldsm_x4_t(b_hi[h], sbase + B_HI + off);
            ldsm_x4_t(b_lo[h], sbase + B_LO + off);
        }
        #pragma unroll
        for (int mt = 0; mt < 2; mt++)
            #pragma unroll
            for (int nt = 0; nt < 4; nt++) {
                const uint32_t* bh = &b_hi[nt >> 1][(nt & 1) * 2];
                const uint32_t* bl = &b_lo[nt >> 1][(nt & 1) * 2];
                mma_bf16(acc[mt][nt], a_hi[mt], bh);
                mma_bf16(acc[mt][nt], a_hi[mt], bl);
                mma_bf16(acc[mt][nt], a_lo[mt], bh);
            }
    }

    const int g  = lane >> 2;
    const int tg = lane & 3;
    #pragma unroll
    for (int mt = 0; mt < 2; mt++)
        #pragma unroll
        for (int rh = 0; rh < 2; rh++) {
            int row = row0 + wm + 16 * mt + g + 8 * rh;
            if (row >= M) continue;
            float di = g_dinv[row];
            #pragma unroll
            for (int nt = 0; nt < 4; nt++) {
                int col = wn + 8 * nt + 2 * tg;
                *(float2*)&C[(size_t)row * 64 + col] =
                    make_float2(acc[mt][nt][2 * rh] * di, acc[mt][nt][2 * rh + 1] * di);
            }
        }
}

// ---------------- CSR gather (R10 structure, 8-wide unroll): out = dd*(Σ h'[s] + h'[node]) ----
template<bool LAYER1>
__global__ __launch_bounds__(256)
void gather_kernel(const float* __restrict__ h, const float* __restrict__ bias,
                   float* __restrict__ zout)
{
    int node = blockIdx.x * 8 + (threadIdx.x >> 5);   // warp per node
    int lane = threadIdx.x & 31;
    if (node >= N_NODES) return;

    const char* hp = (const char*)h + lane * 8;       // lane-fixed base
    float2 a0 = *(const float2*)(hp + (size_t)node * 256);   // self-loop (h' = h*dinv)
    float2 a1 = make_float2(0.f, 0.f);
    float2 a2 = make_float2(0.f, 0.f);
    float2 a3 = make_float2(0.f, 0.f);

    int e   = __ldg(&g_rowptr[node]);
    int end = __ldg(&g_rowptr[node + 1]);
    for (; e + 7 < end; e += 8) {       // 8 independent row loads in flight
        int o0 = __ldg(&g_csr[e]);
        int o1 = __ldg(&g_csr[e + 1]);
        int o2 = __ldg(&g_csr[e + 2]);
        int o3 = __ldg(&g_csr[e + 3]);
        int o4 = __ldg(&g_csr[e + 4]);
        int o5 = __ldg(&g_csr[e + 5]);
        int o6 = __ldg(&g_csr[e + 6]);
        int o7 = __ldg(&g_csr[e + 7]);
        float2 v0 = *(const float2*)(hp + o0);
        float2 v1 = *(const float2*)(hp + o1);
        float2 v2 = *(const float2*)(hp + o2);
        float2 v3 = *(const float2*)(hp + o3);
        float2 v4 = *(const float2*)(hp + o4);
        float2 v5 = *(const float2*)(hp + o5);
        float2 v6 = *(const float2*)(hp + o6);
        float2 v7 = *(const float2*)(hp + o7);
        a0.x += v0.x; a0.y += v0.y;
        a1.x += v1.x; a1.y += v1.y;
        a2.x += v2.x; a2.y += v2.y;
        a3.x += v3.x; a3.y += v3.y;
        a0.x += v4.x; a0.y += v4.y;
        a1.x += v5.x; a1.y += v5.y;
        a2.x += v6.x; a2.y += v6.y;
        a3.x += v7.x; a3.y += v7.y;
    }
    for (; e + 3 < end; e += 4) {
        int o0 = __ldg(&g_csr[e]);
        int o1 = __ldg(&g_csr[e + 1]);
        int o2 = __ldg(&g_csr[e + 2]);
        int o3 = __ldg(&g_csr[e + 3]);
        float2 v0 = *(const float2*)(hp + o0);
        float2 v1 = *(const float2*)(hp + o1);
        float2 v2 = *(const float2*)(hp + o2);
        float2 v3 = *(const float2*)(hp + o3);
        a0.x += v0.x; a0.y += v0.y;
        a1.x += v1.x; a1.y += v1.y;
        a2.x += v2.x; a2.y += v2.y;
        a3.x += v3.x; a3.y += v3.y;
    }
    for (; e < end; e++) {
        int o = __ldg(&g_csr[e]);
        float2 v = *(const float2*)(hp + o);
        a0.x += v.x; a0.y += v.y;
    }
    float dd = g_dinv[node];
    float2 acc = make_float2(((a0.x + a1.x) + (a2.x + a3.x)) * dd,
                             ((a0.y + a1.y) + (a2.y + a3.y)) * dd);

    if (LAYER1) {
        float2 b = *(const float2*)&bias[lane * 2];
        float vx = fmaxf(acc.x + b.x, 0.f);
        float vy = fmaxf(acc.y + b.y, 0.f);
        float hx = bf_hi(vx), hy = bf_hi(vy);
        ((uint32_t*)g_z1hi)[node * 32 + lane] = pack_bf16(hx, hy);
        ((uint32_t*)g_z1lo)[node * 32 + lane] = pack_bf16(vx - hx, vy - hy);
    } else {
        *(float2*)&zout[(size_t)node * 64 + lane * 2] = acc;
    }
}

// ---------------- fused decode: ef -> P1+relu -> P2+relu -> P3 dot ----------------
__global__ __launch_bounds__(256)
void decode_kernel(const int* __restrict__ eli, const float* __restrict__ b2,
                   const float* __restrict__ P1, const float* __restrict__ pb1,
                   const float* __restrict__ P2, const float* __restrict__ pb2,
                   const float* __restrict__ P3, const float* __restrict__ pb3,
                   float* __restrict__ out)
{
    constexpr int SA_H = 72, SB_H = 72;
    constexpr int EF_HI = 0;
    constexpr int EF_LO = 128 * SA_H * 2;
    constexpr int P1_HI = 2 * 128 * SA_H * 2;
    constexpr int P1_LO = P1_HI + 64 * SB_H * 2;
    constexpr int P2_HI = P1_LO + 64 * SB_H * 2;
    constexpr int P2_LO = P2_HI + 64 * SB_H * 2;
    constexpr int S_OUT = P2_LO + 64 * SB_H * 2;

    extern __shared__ char smem[];
    const uint32_t sbase = smem_u32(smem);
    const int tid  = threadIdx.x;
    const int wid  = tid >> 5;
    const int lane = tid & 31;
    const int row0 = blockIdx.x * 128;

    if (tid < 128) *(float*)(smem + S_OUT + tid * 4) = 0.f;

    #pragma unroll
    for (int idx = tid; idx < 128 * 16; idx += 256) {
        int pl = idx >> 4, c4 = (idx & 15) << 2;
        int p = row0 + pl;
        float4 r = make_float4(0.f, 0.f, 0.f, 0.f);
        if (p < N_EL) {
            int a = __ldg(&eli[p]);
            int b = __ldg(&eli[N_EL + p]);
            float4 bb = *(const float4*)&b2[c4];
            float4 za = *(const float4*)&g_z2[a * 64 + c4];
            float4 zb = *(const float4*)&g_z2[b * 64 + c4];
            r.x = (za.x + bb.x) * (zb.x + bb.x);
            r.y = (za.y + bb.y) * (zb.y + bb.y);
            r.z = (za.z + bb.z) * (zb.z + bb.z);
            r.w = (za.w + bb.w) * (zb.w + bb.w);
        }
        float hx = bf_hi(r.x), hy = bf_hi(r.y), hz = bf_hi(r.z), hw = bf_hi(r.w);
        uint32_t off = (uint32_t)(pl * SA_H + c4) * 2;
        *(uint2*)(smem + EF_HI + off) = make_uint2(pack_bf16(hx, hy), pack_bf16(hz, hw));
        *(uint2*)(smem + EF_LO + off) = make_uint2(pack_bf16(r.x - hx, r.y - hy),
                                                   pack_bf16(r.z - hz, r.w - hw));
    }
    #pragma unroll
    for (int idx = tid; idx < 64 * 16; idx += 256) {
        int k = idx >> 4, nc = (idx & 15) << 2;
        uint32_t off = (uint32_t)(k * SB_H + nc) * 2;
        float4 v = *(const float4*)&P1[k * 64 + nc];
        float hx = bf_hi(v.x), hy = bf_hi(v.y), hz = bf_hi(v.z), hw = bf_hi(v.w);
        *(uint2*)(smem + P1_HI + off) = make_uint2(pack_bf16(hx, hy), pack_bf16(hz, hw));
        *(uint2*)(smem + P1_LO + off) = make_uint2(pack_bf16(v.x - hx, v.y - hy),
                                                   pack_bf16(v.z - hz, v.w - hw));
        float4 u = *(const float4*)&P2[k * 64 + nc];
        float ux = bf_hi(u.x), uy = bf_hi(u.y), uz = bf_hi(u.z), uw = bf_hi(u.w);
        *(uint2*)(smem + P2_HI + off) = make_uint2(pack_bf16(ux, uy), pack_bf16(uz, uw));
        *(uint2*)(smem + P2_LO + off) = make_uint2(pack_bf16(u.x - ux, u.y - uy),
                                                   pack_bf16(u.z - uz, u.w - uw));
    }
    __syncthreads();

    const int wm = (wid & 3) * 32;
    const int wn = (wid >> 2) * 32;
    const int lrow = lane & 15;
    const int lsel = (lane >> 4) * 8;
    const int g  = lane >> 2;
    const int tg = lane & 3;

    float acc[2][4][4];
    #pragma unroll
    for (int mt = 0; mt < 2; mt++)
        #pragma unroll
        for (int nt = 0; nt < 4; nt++)
            #pragma unroll
            for (int i = 0; i < 4; i++) acc[mt][nt][i] = 0.f;

    #pragma unroll
    for (int k0 = 0; k0 < 64; k0 += 16) {
        uint32_t a_hi[2][4], a_lo[2][4];
        #pragma unroll
        for (int mt = 0; mt < 2; mt++) {
            uint32_t off = (uint32_t)((wm + 16 * mt + lrow) * SA_H + k0 + lsel) * 2;
            ldsm_x4(a_hi[mt], sbase + EF_HI + off);
            ldsm_x4(a_lo[mt], sbase + EF_LO + off);
        }
        uint32_t b_hi[2][4], b_lo[2][4];
        #pragma unroll
        for (int h = 0; h < 2; h++) {
            uint32_t off = (uint32_t)((k0 + lrow) * SB_H + wn + 16 * h + lsel) * 2;
            ldsm_x4_t(b_hi[h], sbase + P1_HI + off);
            ldsm_x4_t(b_lo[h], sbase + P1_LO + off);
        }
        #pragma unroll
        for (int mt = 0; mt < 2; mt++)
            #pragma unroll
            for (int nt = 0; nt < 4; nt++) {
                const uint32_t* bh = &b_hi[nt >> 1][(nt & 1) * 2];
                const uint32_t* bl = &b_lo[nt >> 1][(nt & 1) * 2];
                mma_bf16(acc[mt][nt], a_hi[mt], bh);
                mma_bf16(acc[mt][nt], a_hi[mt], bl);
                mma_bf16(acc[mt][nt], a_lo[mt], bh);
            }
    }
    __syncthreads();

    #pragma unroll
    for (int mt = 0; mt < 2; mt++)
        #pragma unroll
        for (int rh = 0; rh < 2; rh++) {
            int rl = wm + 16 * mt + g + 8 * rh;
            #pragma unroll
            for (int nt = 0; nt < 4; nt++) {
                int col = wn + 8 * nt + 2 * tg;
                float vx = fmaxf(acc[mt][nt][2 * rh]     + __ldg(&pb1[col]),     0.f);
                float vy = fmaxf(acc[mt][nt][2 * rh + 1] + __ldg(&pb1[col + 1]), 0.f);
                float hx = bf_hi(vx), hy = bf_hi(vy);
                uint32_t off = (uint32_t)(rl * SA_H + col) * 2;
                *(uint32_t*)(smem + EF_HI + off) = pack_bf16(hx, hy);
                *(uint32_t*)(smem + EF_LO + off) = pack_bf16(vx - hx, vy - hy);
            }
        }
    __syncthreads();

    #pragma unroll
    for (int mt = 0; mt < 2; mt++)
        #pragma unroll
        for (int nt = 0; nt < 4; nt++)
            #pragma unroll
            for (int i = 0; i < 4; i++) acc[mt][nt][i] = 0.f;

    #pragma unroll
    for (int k0 = 0; k0 < 64; k0 += 16) {
        uint32_t a_hi[2][4], a_lo[2][4];
        #pragma unroll
        for (int mt = 0; mt < 2; mt++) {
            uint32_t off = (uint32_t)((wm + 16 * mt + lrow) * SA_H + k0 + lsel) * 2;
            ldsm_x4(a_hi[mt], sbase + EF_HI + off);
            ldsm_x4(a_lo[mt], sbase + EF_LO + off);
        }
        uint32_t b_hi[2][4], b_lo[2][4];
        #pragma unroll
        for (int h = 0; h < 2; h++) {
            uint32_t off = (uint32_t)((k0 + lrow) * SB_H + wn + 16 * h + lsel) * 2;
            ldsm_x4_t(b_hi[h], sbase + P2_HI + off);
            ldsm_x4_t(b_lo[h], sbase + P2_LO + off);
        }
        #pragma unroll
        for (int mt = 0; mt < 2; mt++)
            #pragma unroll
            for (int nt = 0; nt < 4; nt++) {
                const uint32_t* bh = &b_hi[nt >> 1][(nt & 1) * 2];
                const uint32_t* bl = &b_lo[nt >> 1][(nt & 1) * 2];
                mma_bf16(acc[mt][nt], a_hi[mt], bh);
                mma_bf16(acc[mt][nt], a_hi[mt], bl);
                mma_bf16(acc[mt][nt], a_lo[mt], bh);
            }
    }

    #pragma unroll
    for (int mt = 0; mt < 2; mt++)
        #pragma unroll
        for (int rh = 0; rh < 2; rh++) {
            float s = 0.f;
            #pragma unroll
            for (int nt = 0; nt < 4; nt++) {
                int col = wn + 8 * nt + 2 * tg;
                float vx = fmaxf(acc[mt][nt][2 * rh]     + __ldg(&pb2[col]),     0.f);
                float vy = fmaxf(acc[mt][nt][2 * rh + 1] + __ldg(&pb2[col + 1]), 0.f);
                s += vx * __ldg(&P3[col]) + vy * __ldg(&P3[col + 1]);
            }
            s += __shfl_xor_sync(0xffffffffu, s, 1);
            s += __shfl_xor_sync(0xffffffffu, s, 2);
            if (tg == 0) {
                int rl = wm + 16 * mt + g + 8 * rh;
                atomicAdd((float*)(smem + S_OUT) + rl, s);
            }
        }
    __syncthreads();
    if (tid < 128) {
        int p = row0 + tid;
        if (p < N_EL) out[p] = *(float*)(smem + S_OUT + tid * 4) + __ldg(&pb3[0]);
    }
}

// ---------------- launcher ----------------
extern "C" void kernel_launch(void* const* d_in, const int* in_sizes, int n_in,
                              void* d_out, int out_size)
{
    const float* x   = (const float*)d_in[0];
    const int*   ei  = (const int*)  d_in[1];
    const int*   eli = (const int*)  d_in[2];
    const float* W1  = (const float*)d_in[3];
    const float* b1  = (const float*)d_in[4];
    const float* W2  = (const float*)d_in[5];
    const float* b2  = (const float*)d_in[6];
    const float* P1  = (const float*)d_in[7];
    const float* pb1 = (const float*)d_in[8];
    const float* P2  = (const float*)d_in[9];
    const float* pb2 = (const float*)d_in[10];
    const float* P3  = (const float*)d_in[11];
    const float* pb3 = (const float*)d_in[12];
    float* out = (float*)d_out;

    const int* src = ei;
    const int* dst = ei + N_EDGES;

    float *ph1, *ph2, *pz2;
    cudaGetSymbolAddress((void**)&ph1, g_h1);
    cudaGetSymbolAddress((void**)&ph2, g_h2);
    cudaGetSymbolAddress((void**)&pz2, g_z2);
    __nv_bfloat16 *pxhi, *pxlo, *pz1hi, *pz1lo, *pw1hi, *pw1lo, *pw2hi, *pw2lo;
    cudaGetSymbolAddress((void**)&pxhi,  g_xhi);
    cudaGetSymbolAddress((void**)&pxlo,  g_xlo);
    cudaGetSymbolAddress((void**)&pz1hi, g_z1hi);
    cudaGetSymbolAddress((void**)&pz1lo, g_z1lo);
    cudaGetSymbolAddress((void**)&pw1hi, g_w1hi);
    cudaGetSymbolAddress((void**)&pw1lo, g_w1lo);
    cudaGetSymbolAddress((void**)&pw2hi, g_w2hi);
    cudaGetSymbolAddress((void**)&pw2lo, g_w2lo);

    const int SM128 = 2 * 128 * (128 + 8) * 2 + 2 * 128 * 72 * 2;  // 106496
    const int SM64  = 2 * 128 * (64 + 8) * 2  + 2 * 64 * 72 * 2;   //  55296
    const int SMDEC = 2 * 128 * 72 * 2 + 6 * 64 * 72 * 2 + 512;    //  74240
    cudaFuncSetAttribute(scan_gemm1_kernel, cudaFuncAttributeMaxDynamicSharedMemorySize, SM128);
    cudaFuncSetAttribute(mma_gemm_pre<64>,  cudaFuncAttributeMaxDynamicSharedMemorySize, SM64);
    cudaFuncSetAttribute(decode_kernel,     cudaFuncAttributeMaxDynamicSharedMemorySize, SMDEC);

    const int gbN  = (N_NODES + 127) / 128;   // 391
    const int gbEL = (N_EL    + 127) / 128;   // 782
    const int gbG  = (N_NODES + 7) / 8;       // 6250

    // K1: degree count + operand splits (degi starts at 0 by invariant)
    prep_count_kernel<<<CB + XB + W1B + W2B, 256>>>(dst, x, W1, W2);
    // K2: lookback scan (+dinv) fused with gemm1; epilogue scales by dinv after scan-done
    scan_gemm1_kernel<<<NSCAN_BLOCKS + gbN, 256, SM128>>>(pxhi, pxlo, pw1hi, pw1lo, ph1, N_NODES);
    // K3: CSR fill (byte offsets; restores degi=0, scanstate=0, scandone=0)
    fill_csr_kernel<<<CB, 256>>>(src, dst);
    // gather layer 1 (+bias+relu+split fused)
    gather_kernel<true><<<gbG, 256>>>(ph1, b1, nullptr);
    // conv layer 2 (epilogue scaled by dinv)
    mma_gemm_pre<64><<<gbN, 256, SM64>>>(pz1hi, pz1lo, pw2hi, pw2lo, ph2, N_NODES);
    gather_kernel<false><<<gbG, 256>>>(ph2, nullptr, pz2);
    // fused decode
    decode_kernel<<<gbEL, 256, SMDEC>>>(eli, b2, P1, pb1, P2, pb2, P3, pb3, out);
}

// round 13
// speedup vs baseline: 1.5507x; 1.0581x over previous
#include <cuda_runtime.h>
#include <cuda_bf16.h>
#include <cuda_fp16.h>
#include <cstdint>

#define N_NODES 50000
#define N_EDGES 800000
#define N_EL    100000
#define NSCAN_BLOCKS ((N_NODES + 255) / 256)   // 196

// ---------------- scratch (device globals; no allocation allowed) ----------------
// INVARIANT: g_degi, g_scanstate, g_scandone are zero at the start of every run.
// (zero-initialized at module load; fill_csr_kernel restores them each run)
__device__ int      g_degi     [N_NODES];
__device__ uint32_t g_scanstate[NSCAN_BLOCKS];
__device__ int      g_scandone;
__device__ int      g_rowptr   [N_NODES + 1];
__device__ int      g_csr      [N_EDGES];      // BYTE offsets: src*128 (fp16 rows)
__device__ float g_dinv[N_NODES];
__device__ __half g_h1 [N_NODES * 64];         // fp16, scaled: h1*dinv[row]
__device__ __half g_h2 [N_NODES * 64];         // fp16, scaled: h2*dinv[row]
__device__ float g_z2  [N_NODES * 64];
// pre-split bf16 operand arrays
__device__ __nv_bfloat16 g_xhi [N_NODES * 128];
__device__ __nv_bfloat16 g_xlo [N_NODES * 128];
__device__ __nv_bfloat16 g_z1hi[N_NODES * 64];
__device__ __nv_bfloat16 g_z1lo[N_NODES * 64];
__device__ __nv_bfloat16 g_w1hi[128 * 64];
__device__ __nv_bfloat16 g_w1lo[128 * 64];
__device__ __nv_bfloat16 g_w2hi[64 * 64];
__device__ __nv_bfloat16 g_w2lo[64 * 64];

// ---------------- helpers ----------------
__device__ __forceinline__ uint32_t smem_u32(const void* p) {
    uint32_t a;
    asm("{ .reg .u64 t; cvta.to.shared.u64 t, %1; cvt.u32.u64 %0, t; }" : "=r"(a) : "l"(p));
    return a;
}
__device__ __forceinline__ uint32_t pack_bf16(float x, float y) {
    __nv_bfloat162 t = __floats2bfloat162_rn(x, y);
    return *(uint32_t*)&t;
}
__device__ __forceinline__ float bf_hi(float x) {
    return __bfloat162float(__float2bfloat16_rn(x));
}
__device__ __forceinline__ void cp16(uint32_t dst, const void* src, uint32_t sz) {
    asm volatile("cp.async.ca.shared.global [%0], [%1], 16, %2;"
                 :: "r"(dst), "l"(src), "r"(sz) : "memory");
}
__device__ __forceinline__ void cp_commit_wait() {
    asm volatile("cp.async.commit_group;");
    asm volatile("cp.async.wait_group 0;" ::: "memory");
}
__device__ __forceinline__ void ldsm_x4(uint32_t* r, uint32_t addr) {
    asm volatile("ldmatrix.sync.aligned.m8n8.x4.shared.b16 {%0,%1,%2,%3}, [%4];"
                 : "=r"(r[0]), "=r"(r[1]), "=r"(r[2]), "=r"(r[3]) : "r"(addr));
}
__device__ __forceinline__ void ldsm_x4_t(uint32_t* r, uint32_t addr) {
    asm volatile("ldmatrix.sync.aligned.m8n8.x4.trans.shared.b16 {%0,%1,%2,%3}, [%4];"
                 : "=r"(r[0]), "=r"(r[1]), "=r"(r[2]), "=r"(r[3]) : "r"(addr));
}
__device__ __forceinline__ void mma_bf16(float* d, const uint32_t* a, const uint32_t* b) {
    asm volatile("mma.sync.aligned.m16n8k16.row.col.f32.bf16.bf16.f32 "
                 "{%0,%1,%2,%3}, {%4,%5,%6,%7}, {%8,%9}, {%0,%1,%2,%3};"
                 : "+f"(d[0]), "+f"(d[1]), "+f"(d[2]), "+f"(d[3])
                 : "r"(a[0]), "r"(a[1]), "r"(a[2]), "r"(a[3]), "r"(b[0]), "r"(b[1]));
}
__device__ __forceinline__ void split_store(const float* __restrict__ in,
                                            __nv_bfloat16* __restrict__ hi,
                                            __nv_bfloat16* __restrict__ lo, int i) {
    float4 v = ((const float4*)in)[i];
    float hx = bf_hi(v.x), hy = bf_hi(v.y), hz = bf_hi(v.z), hw = bf_hi(v.w);
    ((uint2*)hi)[i] = make_uint2(pack_bf16(hx, hy), pack_bf16(hz, hw));
    ((uint2*)lo)[i] = make_uint2(pack_bf16(v.x - hx, v.y - hy), pack_bf16(v.z - hz, v.w - hw));
}
__device__ __forceinline__ int warp_incl_scan(int v, int lane) {
    #pragma unroll
    for (int o = 1; o < 32; o <<= 1) {
        int t = __shfl_up_sync(0xffffffffu, v, o);
        if (lane >= o) v += t;
    }
    return v;
}

// ---------------- K1: degree count + all operand splits (range-dispatched) ----------------
#define CB  ((N_EDGES + 255) / 256)          // 3125 blocks: count degrees
#define XB  ((N_NODES * 32 + 255) / 256)     // 6250 blocks: split x
#define W1B ((128 * 16 + 255) / 256)         // 8 blocks
#define W2B ((64 * 16 + 255) / 256)          // 4 blocks
__global__ void prep_count_kernel(const int* __restrict__ dst, const float* __restrict__ x,
                                  const float* __restrict__ W1, const float* __restrict__ W2) {
    int b = blockIdx.x;
    if (b < CB) {
        int e = b * 256 + threadIdx.x;
        if (e < N_EDGES) atomicAdd(&g_degi[dst[e]], 1);   // degi starts at 0 (invariant)
    } else if (b < CB + XB) {
        int i = (b - CB) * 256 + threadIdx.x;
        if (i < N_NODES * 32) split_store(x, g_xhi, g_xlo, i);
    } else if (b < CB + XB + W1B) {
        int i = (b - CB - XB) * 256 + threadIdx.x;
        if (i < 128 * 16) split_store(W1, g_w1hi, g_w1lo, i);
    } else {
        int i = (b - CB - XB - W1B) * 256 + threadIdx.x;
        if (i < 64 * 16) split_store(W2, g_w2hi, g_w2lo, i);
    }
}

// ---------------- K2: decoupled-lookback scan (+dinv) fused with gemm1 ----------------
#define FLAG_AGG (1u << 30)
#define FLAG_PRE (2u << 30)
#define VAL_MASK 0x3FFFFFFFu

__device__ __forceinline__ void scan_block_body(int b) {
    __shared__ int wsum[8];
    __shared__ int s_base;
    int i = b * 256 + threadIdx.x;
    int lane = threadIdx.x & 31, w = threadIdx.x >> 5;

    int d = (i < N_NODES) ? g_degi[i] : 0;
    if (i < N_NODES) g_dinv[i] = rsqrtf((float)d + 1.0f);   // +1 = self-loop
    int s = warp_incl_scan(d, lane);
    if (lane == 31) wsum[w] = s;
    __syncthreads();
    if (w == 0) {
        int ws = (lane < 8) ? wsum[lane] : 0;
        ws = warp_incl_scan(ws, lane);
        if (lane < 8) wsum[lane] = ws;
    }
    __syncthreads();
    int base = (w > 0) ? wsum[w - 1] : 0;
    int incl = base + s;                 // inclusive within block
    uint32_t blocksum = (uint32_t)wsum[7];

    if (threadIdx.x == 0) {
        if (b == 0) {
            atomicExch(&g_scanstate[0], FLAG_PRE | blocksum);
            s_base = 0;
        } else {
            atomicExch(&g_scanstate[b], FLAG_AGG | blocksum);
        }
    }
    if (b > 0 && w == 0) {               // warp 0 lookback
        uint32_t exc = 0;
        int look = b - 1;
        while (true) {
            int idx = look - lane;
            uint32_t f = 0, val = 0;
            if (idx >= 0) {
                uint32_t v;
                do { v = atomicAdd(&g_scanstate[idx], 0u); } while ((v >> 30) == 0u);
                f = v >> 30;
                val = v & VAL_MASK;
            }
            unsigned pm = __ballot_sync(0xffffffffu, f == 2u);
            if (pm) {
                int cut = __ffs(pm) - 1;
                if (lane > cut) val = 0;
            }
            #pragma unroll
            for (int o = 16; o > 0; o >>= 1) val += __shfl_xor_sync(0xffffffffu, val, o);
            exc += val;
            if (pm) break;
            look -= 32;
        }
        if (lane == 0) {
            s_base = (int)exc;
            atomicExch(&g_scanstate[b], FLAG_PRE | (exc + blocksum));
        }
    }
    __syncthreads();
    if (i < N_NODES) g_rowptr[i] = s_base + incl - d;       // exclusive
    if (i == 0) g_rowptr[N_NODES] = N_EDGES;
    // signal dinv/rowptr complete (gemm epilogues wait on this)
    __syncthreads();
    if (threadIdx.x == 0) {
        __threadfence();
        atomicAdd(&g_scandone, 1);
    }
}

__global__ __launch_bounds__(256)
void scan_gemm1_kernel(const __nv_bfloat16* __restrict__ Ahi, const __nv_bfloat16* __restrict__ Alo,
                       const __nv_bfloat16* __restrict__ Bhi, const __nv_bfloat16* __restrict__ Blo,
                       __half* __restrict__ C, int M)
{
    if (blockIdx.x < NSCAN_BLOCKS) { scan_block_body(blockIdx.x); return; }

    constexpr int K = 128;
    constexpr int SA_H = K + 8;
    constexpr int SB_H = 72;
    constexpr int A_HI = 0;
    constexpr int A_LO = 128 * SA_H * 2;
    constexpr int B_HI = 2 * 128 * SA_H * 2;
    constexpr int B_LO = B_HI + K * SB_H * 2;

    extern __shared__ char smem[];
    const uint32_t sbase = smem_u32(smem);
    const int tid  = threadIdx.x;
    const int wid  = tid >> 5;
    const int lane = tid & 31;
    const int row0 = (blockIdx.x - NSCAN_BLOCKS) * 128;

    constexpr int ACH = K / 8;
    #pragma unroll
    for (int idx = tid; idx < 128 * ACH; idx += 256) {
        int r  = idx / ACH;
        int kc = (idx - r * ACH) * 8;
        int row = row0 + r;
        uint32_t sz = (row < M) ? 16u : 0u;
        size_t goff = (size_t)(row < M ? row : 0) * K + kc;
        uint32_t d = sbase + A_HI + (uint32_t)(r * SA_H + kc) * 2;
        cp16(d,                 &Ahi[goff], sz);
        cp16(d + (A_LO - A_HI), &Alo[goff], sz);
    }
    #pragma unroll
    for (int idx = tid; idx < K * 8; idx += 256) {
        int k = idx >> 3, nc = (idx & 7) * 8;
        uint32_t d = sbase + B_HI + (uint32_t)(k * SB_H + nc) * 2;
        cp16(d,                 &Bhi[k * 64 + nc], 16u);
        cp16(d + (B_LO - B_HI), &Blo[k * 64 + nc], 16u);
    }
    cp_commit_wait();
    __syncthreads();

    const int wm = (wid & 3) * 32;
    const int wn = (wid >> 2) * 32;
    const int lrow = lane & 15;
    const int lsel = (lane >> 4) * 8;

    float acc[2][4][4];
    #pragma unroll
    for (int mt = 0; mt < 2; mt++)
        #pragma unroll
        for (int nt = 0; nt < 4; nt++)
            #pragma unroll
            for (int i = 0; i < 4; i++) acc[mt][nt][i] = 0.f;

    #pragma unroll
    for (int k0 = 0; k0 < K; k0 += 16) {
        uint32_t a_hi[2][4], a_lo[2][4];
        #pragma unroll
        for (int mt = 0; mt < 2; mt++) {
            uint32_t off = (uint32_t)((wm + 16 * mt + lrow) * SA_H + k0 + lsel) * 2;
            ldsm_x4(a_hi[mt], sbase + A_HI + off);
            ldsm_x4(a_lo[mt], sbase + A_LO + off);
        }
        uint32_t b_hi[2][4], b_lo[2][4];
        #pragma unroll
        for (int h = 0; h < 2; h++) {
            uint32_t off = (uint32_t)((k0 + lrow) * SB_H + wn + 16 * h + lsel) * 2;
            ldsm_x4_t(b_hi[h], sbase + B_HI + off);
            ldsm_x4_t(b_lo[h], sbase + B_LO + off);
        }
        #pragma unroll
        for (int mt = 0; mt < 2; mt++)
            #pragma unroll
            for (int nt = 0; nt < 4; nt++) {
                const uint32_t* bh = &b_hi[nt >> 1][(nt & 1) * 2];
                const uint32_t* bl = &b_lo[nt >> 1][(nt & 1) * 2];
                mma_bf16(acc[mt][nt], a_hi[mt], bh);
                mma_bf16(acc[mt][nt], a_hi[mt], bl);
                mma_bf16(acc[mt][nt], a_lo[mt], bh);
            }
    }

    // wait for scan blocks (dinv ready); one thread spins, all sync after
    __shared__ int s_ready;
    if (tid == 0) {
        while (atomicAdd(&g_scandone, 0) < NSCAN_BLOCKS) {}
        __threadfence();
        s_ready = 1;
    }
    __syncthreads();

    const int g  = lane >> 2;
    const int tg = lane & 3;
    #pragma unroll
    for (int mt = 0; mt < 2; mt++)
        #pragma unroll
        for (int rh = 0; rh < 2; rh++) {
            int row = row0 + wm + 16 * mt + g + 8 * rh;
            if (row >= M) continue;
            float di = g_dinv[row];
            #pragma unroll
            for (int nt = 0; nt < 4; nt++) {
                int col = wn + 8 * nt + 2 * tg;
                ((__half2*)C)[row * 32 + (col >> 1)] =
                    __floats2half2_rn(acc[mt][nt][2 * rh] * di, acc[mt][nt][2 * rh + 1] * di);
            }
        }
}

// ---------------- K3: fill CSR (byte offsets for 128B fp16 rows; restores invariants) ----------------
__global__ void fill_csr_kernel(const int* __restrict__ src, const int* __restrict__ dst) {
    int e = blockIdx.x * 256 + threadIdx.x;
    if (blockIdx.x == 0) {
        if (threadIdx.x < NSCAN_BLOCKS) g_scanstate[threadIdx.x] = 0u;
        if (threadIdx.x == 0) g_scandone = 0;
    }
    if (e >= N_EDGES) return;
    int d = dst[e];
    int old = atomicSub(&g_degi[d], 1);      // degi returns to 0 after this kernel
    g_csr[g_rowptr[d] + old - 1] = src[e] << 7;   // byte offset: src*128
}

// ---------------- pre-split mma GEMM (layer 2), epilogue scaled by dinv, fp16 out ----------------
template<int K>
__global__ __launch_bounds__(256)
void mma_gemm_pre(const __nv_bfloat16* __restrict__ Ahi, const __nv_bfloat16* __restrict__ Alo,
                  const __nv_bfloat16* __restrict__ Bhi, const __nv_bfloat16* __restrict__ Blo,
                  __half* __restrict__ C, int M)
{
    constexpr int SA_H = K + 8;
    constexpr int SB_H = 72;
    constexpr int A_HI = 0;
    constexpr int A_LO = 128 * SA_H * 2;
    constexpr int B_HI = 2 * 128 * SA_H * 2;
    constexpr int B_LO = B_HI + K * SB_H * 2;

    extern __shared__ char smem[];
    const uint32_t sbase = smem_u32(smem);
    const int tid  = threadIdx.x;
    const int wid  = tid >> 5;
    const int lane = tid & 31;
    const int row0 = blockIdx.x * 128;

    constexpr int ACH = K / 8;
    #pragma unroll
    for (int idx = tid; idx < 128 * ACH; idx += 256) {
        int r  = idx / ACH;
        int kc = (idx - r * ACH) * 8;
        int row = row0 + r;
        uint32_t sz = (row < M) ? 16u : 0u;
        size_t goff = (size_t)(row < M ? row : 0) * K + kc;
        uint32_t d = sbase + A_HI + (uint32_t)(r * SA_H + kc) * 2;
        cp16(d,                 &Ahi[goff], sz);
        cp16(d + (A_LO - A_HI), &Alo[goff], sz);
    }
    #pragma unroll
    for (int idx = tid; idx < K * 8; idx += 256) {
        int k = idx >> 3, nc = (idx & 7) * 8;
        uint32_t d = sbase + B_HI + (uint32_t)(k * SB_H + nc) * 2;
        cp16(d,                 &Bhi[k * 64 + nc], 16u);
        cp16(d + (B_LO - B_HI), &Blo[k * 64 + nc], 16u);
    }
    cp_commit_wait();
    __syncthreads();

    const int wm = (wid & 3) * 32;
    const int wn = (wid >> 2) * 32;
    const int lrow = lane & 15;
    const int lsel = (lane >> 4) * 8;

    float acc[2][4][4];
    #pragma unroll
    for (int mt = 0; mt < 2; mt++)
        #pragma unroll
        for (int nt = 0; nt < 4; nt++)
            #pragma unroll
            for (int i = 0; i < 4; i++) acc[mt][nt][i] = 0.f;

    #pragma unroll
    for (int k0 = 0; k0 < K; k0 += 16) {
        uint32_t a_hi[2][4], a_lo[2][4];
        #pragma unroll
        for (int mt = 0; mt < 2; mt++) {
            uint32_t off = (uint32_t)((wm + 16 * mt + lrow) * SA_H + k0 + lsel) * 2;
            ldsm_x4(a_hi[mt], sbase + A_HI + off);
            ldsm_x4(a_lo[mt], sbase + A_LO + off);
        }
        uint32_t b_hi[2][4], b_lo[2][4];
        #pragma unroll
        for (int h = 0; h < 2; h++) {
            uint32_t off = (uint32_t)((k0 + lrow) * SB_H + wn + 16 * h + lsel) * 2;
            ldsm_x4_t(b_hi[h], sbase + B_HI + off);
            ldsm_x4_t(b_lo[h], sbase + B_LO + off);
        }
        #pragma unroll
        for (int mt = 0; mt < 2; mt++)
            #pragma unroll
            for (int nt = 0; nt < 4; nt++) {
                const uint32_t* bh = &b_hi[nt >> 1][(nt & 1) * 2];
                const uint32_t* bl = &b_lo[nt >> 1][(nt & 1) * 2];
                mma_bf16(acc[mt][nt], a_hi[mt], bh);
                mma_bf16(acc[mt][nt], a_hi[mt], bl);
                mma_bf16(acc[mt][nt], a_lo[mt], bh);
            }
    }

    const int g  = lane >> 2;
    const int tg = lane & 3;
    #pragma unroll
    for (int mt = 0; mt < 2; mt++)
        #pragma unroll
        for (int rh = 0; rh < 2; rh++) {
            int row = row0 + wm + 16 * mt + g + 8 * rh;
            if (row >= M) continue;
            float di = g_dinv[row];
            #pragma unroll
            for (int nt = 0; nt < 4; nt++) {
                int col = wn + 8 * nt + 2 * tg;
                ((__half2*)C)[row * 32 + (col >> 1)] =
                    __floats2half2_rn(acc[mt][nt][2 * rh] * di, acc[mt][nt][2 * rh + 1] * di);
            }
        }
}

// ---------------- CSR gather (fp16 rows, 4-wide unroll): out = dd*(Σ h'[s] + h'[node]) ----
template<bool LAYER1>
__global__ __launch_bounds__(256)
void gather_kernel(const __half* __restrict__ h, const float* __restrict__ bias,
                   float* __restrict__ zout)
{
    int node = blockIdx.x * 8 + (threadIdx.x >> 5);   // warp per node
    int lane = threadIdx.x & 31;
    if (node >= N_NODES) return;

    const char* hp = (const char*)h + lane * 4;       // lane-fixed base (half2 per lane)
    float2 a0 = __half22float2(*(const __half2*)(hp + (size_t)node * 128));  // self-loop
    float2 a1 = make_float2(0.f, 0.f);
    float2 a2 = make_float2(0.f, 0.f);
    float2 a3 = make_float2(0.f, 0.f);

    int e   = __ldg(&g_rowptr[node]);
    int end = __ldg(&g_rowptr[node + 1]);
    for (; e + 3 < end; e += 4) {
        int o0 = __ldg(&g_csr[e]);
        int o1 = __ldg(&g_csr[e + 1]);
        int o2 = __ldg(&g_csr[e + 2]);
        int o3 = __ldg(&g_csr[e + 3]);
        float2 v0 = __half22float2(*(const __half2*)(hp + o0));
        float2 v1 = __half22float2(*(const __half2*)(hp + o1));
        float2 v2 = __half22float2(*(const __half2*)(hp + o2));
        float2 v3 = __half22float2(*(const __half2*)(hp + o3));
        a0.x += v0.x; a0.y += v0.y;
        a1.x += v1.x; a1.y += v1.y;
        a2.x += v2.x; a2.y += v2.y;
        a3.x += v3.x; a3.y += v3.y;
    }
    for (; e < end; e++) {
        int o = __ldg(&g_csr[e]);
        float2 v = __half22float2(*(const __half2*)(hp + o));
        a0.x += v.x; a0.y += v.y;
    }
    float dd = g_dinv[node];
    float2 acc = make_float2(((a0.x + a1.x) + (a2.x + a3.x)) * dd,
                             ((a0.y + a1.y) + (a2.y + a3.y)) * dd);

    if (LAYER1) {
        float2 b = *(const float2*)&bias[lane * 2];
        float vx = fmaxf(acc.x + b.x, 0.f);
        float vy = fmaxf(acc.y + b.y, 0.f);
        float hx = bf_hi(vx), hy = bf_hi(vy);
        ((uint32_t*)g_z1hi)[node * 32 + lane] = pack_bf16(hx, hy);
        ((uint32_t*)g_z1lo)[node * 32 + lane] = pack_bf16(vx - hx, vy - hy);
    } else {
        *(float2*)&zout[(size_t)node * 64 + lane * 2] = acc;
    }
}

// ---------------- fused decode: ef -> P1+relu -> P2+relu -> P3 dot ----------------
__global__ __launch_bounds__(256)
void decode_kernel(const int* __restrict__ eli, const float* __restrict__ b2,
                   const float* __restrict__ P1, const float* __restrict__ pb1,
                   const float* __restrict__ P2, const float* __restrict__ pb2,
                   const float* __restrict__ P3, const float* __restrict__ pb3,
                   float* __restrict__ out)
{
    constexpr int SA_H = 72, SB_H = 72;
    constexpr int EF_HI = 0;
    constexpr int EF_LO = 128 * SA_H * 2;
    constexpr int P1_HI = 2 * 128 * SA_H * 2;
    constexpr int P1_LO = P1_HI + 64 * SB_H * 2;
    constexpr int P2_HI = P1_LO + 64 * SB_H * 2;
    constexpr int P2_LO = P2_HI + 64 * SB_H * 2;
    constexpr int S_OUT = P2_LO + 64 * SB_H * 2;

    extern __shared__ char smem[];
    const uint32_t sbase = smem_u32(smem);
    const int tid  = threadIdx.x;
    const int wid  = tid >> 5;
    const int lane = tid & 31;
    const int row0 = blockIdx.x * 128;

    if (tid < 128) *(float*)(smem + S_OUT + tid * 4) = 0.f;

    #pragma unroll
    for (int idx = tid; idx < 128 * 16; idx += 256) {
        int pl = idx >> 4, c4 = (idx & 15) << 2;
        int p = row0 + pl;
        float4 r = make_float4(0.f, 0.f, 0.f, 0.f);
        if (p < N_EL) {
            int a = __ldg(&eli[p]);
            int b = __ldg(&eli[N_EL + p]);
            float4 bb = *(const float4*)&b2[c4];
            float4 za = *(const float4*)&g_z2[a * 64 + c4];
            float4 zb = *(const float4*)&g_z2[b * 64 + c4];
            r.x = (za.x + bb.x) * (zb.x + bb.x);
            r.y = (za.y + bb.y) * (zb.y + bb.y);
            r.z = (za.z + bb.z) * (zb.z + bb.z);
            r.w = (za.w + bb.w) * (zb.w + bb.w);
        }
        float hx = bf_hi(r.x), hy = bf_hi(r.y), hz = bf_hi(r.z), hw = bf_hi(r.w);
        uint32_t off = (uint32_t)(pl * SA_H + c4) * 2;
        *(uint2*)(smem + EF_HI + off) = make_uint2(pack_bf16(hx, hy), pack_bf16(hz, hw));
        *(uint2*)(smem + EF_LO + off) = make_uint2(pack_bf16(r.x - hx, r.y - hy),
                                                   pack_bf16(r.z - hz, r.w - hw));
    }
    #pragma unroll
    for (int idx = tid; idx < 64 * 16; idx += 256) {
        int k = idx >> 4, nc = (idx & 15) << 2;
        uint32_t off = (uint32_t)(k * SB_H + nc) * 2;
        float4 v = *(const float4*)&P1[k * 64 + nc];
        float hx = bf_hi(v.x), hy = bf_hi(v.y), hz = bf_hi(v.z), hw = bf_hi(v.w);
        *(uint2*)(smem + P1_HI + off) = make_uint2(pack_bf16(hx, hy), pack_bf16(hz, hw));
        *(uint2*)(smem + P1_LO + off) = make_uint2(pack_bf16(v.x - hx, v.y - hy),
                                                   pack_bf16(v.z - hz, v.w - hw));
        float4 u = *(const float4*)&P2[k * 64 + nc];
        float ux = bf_hi(u.x), uy = bf_hi(u.y), uz = bf_hi(u.z), uw = bf_hi(u.w);
        *(uint2*)(smem + P2_HI + off) = make_uint2(pack_bf16(ux, uy), pack_bf16(uz, uw));
        *(uint2*)(smem + P2_LO + off) = make_uint2(pack_bf16(u.x - ux, u.y - uy),
                                                   pack_bf16(u.z - uz, u.w - uw));
    }
    __syncthreads();

    const int wm = (wid & 3) * 32;
    const int wn = (wid >> 2) * 32;
    const int lrow = lane & 15;
    const int lsel = (lane >> 4) * 8;
    const int g  = lane >> 2;
    const int tg = lane & 3;

    float acc[2][4][4];
    #pragma unroll
    for (int mt = 0; mt < 2; mt++)
        #pragma unroll
        for (int nt = 0; nt < 4; nt++)
            #pragma unroll
            for (int i = 0; i < 4; i++) acc[mt][nt][i] = 0.f;

    #pragma unroll
    for (int k0 = 0; k0 < 64; k0 += 16) {
        uint32_t a_hi[2][4], a_lo[2][4];
        #pragma unroll
        for (int mt = 0; mt < 2; mt++) {
            uint32_t off = (uint32_t)((wm + 16 * mt + lrow) * SA_H + k0 + lsel) * 2;
            ldsm_x4(a_hi[mt], sbase + EF_HI + off);
            ldsm_x4(a_lo[mt], sbase + EF_LO + off);
        }
        uint32_t b_hi[2][4], b_lo[2][4];
        #pragma unroll
        for (int h = 0; h < 2; h++) {
            uint32_t off = (uint32_t)((k0 + lrow) * SB_H + wn + 16 * h + lsel) * 2;
            ldsm_x4_t(b_hi[h], sbase + P1_HI + off);
            ldsm_x4_t(b_lo[h], sbase + P1_LO + off);
        }
        #pragma unroll
        for (int mt = 0; mt < 2; mt++)
            #pragma unroll
            for (int nt = 0; nt < 4; nt++) {
                const uint32_t* bh = &b_hi[nt >> 1][(nt & 1) * 2];
                const uint32_t* bl = &b_lo[nt >> 1][(nt & 1) * 2];
                mma_bf16(acc[mt][nt], a_hi[mt], bh);
                mma_bf16(acc[mt][nt], a_hi[mt], bl);
                mma_bf16(acc[mt][nt], a_lo[mt], bh);
            }
    }
    __syncthreads();

    #pragma unroll
    for (int mt = 0; mt < 2; mt++)
        #pragma unroll
        for (int rh = 0; rh < 2; rh++) {
            int rl = wm + 16 * mt + g + 8 * rh;
            #pragma unroll
            for (int nt = 0; nt < 4; nt++) {
                int col = wn + 8 * nt + 2 * tg;
                float vx = fmaxf(acc[mt][nt][2 * rh]     + __ldg(&pb1[col]),     0.f);
                float vy = fmaxf(acc[mt][nt][2 * rh + 1] + __ldg(&pb1[col + 1]), 0.f);
                float hx = bf_hi(vx), hy = bf_hi(vy);
                uint32_t off = (uint32_t)(rl * SA_H + col) * 2;
                *(uint32_t*)(smem + EF_HI + off) = pack_bf16(hx, hy);
                *(uint32_t*)(smem + EF_LO + off) = pack_bf16(vx - hx, vy - hy);
            }
        }
    __syncthreads();

    #pragma unroll
    for (int mt = 0; mt < 2; mt++)
        #pragma unroll
        for (int nt = 0; nt < 4; nt++)
            #pragma unroll
            for (int i = 0; i < 4; i++) acc[mt][nt][i] = 0.f;

    #pragma unroll
    for (int k0 = 0; k0 < 64; k0 += 16) {
        uint32_t a_hi[2][4], a_lo[2][4];
        #pragma unroll
        for (int mt = 0; mt < 2; mt++) {
            uint32_t off = (uint32_t)((wm + 16 * mt + lrow) * SA_H + k0 + lsel) * 2;
            ldsm_x4(a_hi[mt], sbase + EF_HI + off);
            ldsm_x4(a_lo[mt], sbase + EF_LO + off);
        }
        uint32_t b_hi[2][4], b_lo[2][4];
        #pragma unroll
        for (int h = 0; h < 2; h++) {
            uint32_t off = (uint32_t)((k0 + lrow) * SB_H + wn + 16 * h + lsel) * 2;
            ldsm_x4_t(b_hi[h], sbase + P2_HI + off);
            ldsm_x4_t(b_lo[h], sbase + P2_LO + off);
        }
        #pragma unroll
        for (int mt = 0; mt < 2; mt++)
            #pragma unroll
            for (int nt = 0; nt < 4; nt++) {
                const uint32_t* bh = &b_hi[nt >> 1][(nt & 1) * 2];
                const uint32_t* bl = &b_lo[nt >> 1][(nt & 1) * 2];
                mma_bf16(acc[mt][nt], a_hi[mt], bh);
                mma_bf16(acc[mt][nt], a_hi[mt], bl);
                mma_bf16(acc[mt][nt], a_lo[mt], bh);
            }
    }

    #pragma unroll
    for (int mt = 0; mt < 2; mt++)
        #pragma unroll
        for (int rh = 0; rh < 2; rh++) {
            float s = 0.f;
            #pragma unroll
            for (int nt = 0; nt < 4; nt++) {
                int col = wn + 8 * nt + 2 * tg;
                float vx = fmaxf(acc[mt][nt][2 * rh]     + __ldg(&pb2[col]),     0.f);
                float vy = fmaxf(acc[mt][nt][2 * rh + 1] + __ldg(&pb2[col + 1]), 0.f);
                s += vx * __ldg(&P3[col]) + vy * __ldg(&P3[col + 1]);
            }
            s += __shfl_xor_sync(0xffffffffu, s, 1);
            s += __shfl_xor_sync(0xffffffffu, s, 2);
            if (tg == 0) {
                int rl = wm + 16 * mt + g + 8 * rh;
                atomicAdd((float*)(smem + S_OUT) + rl, s);
            }
        }
    __syncthreads();
    if (tid < 128) {
        int p = row0 + tid;
        if (p < N_EL) out[p] = *(float*)(smem + S_OUT + tid * 4) + __ldg(&pb3[0]);
    }
}

// ---------------- launcher ----------------
extern "C" void kernel_launch(void* const* d_in, const int* in_sizes, int n_in,
                              void* d_out, int out_size)
{
    const float* x   = (const float*)d_in[0];
    const int*   ei  = (const int*)  d_in[1];
    const int*   eli = (const int*)  d_in[2];
    const float* W1  = (const float*)d_in[3];
    const float* b1  = (const float*)d_in[4];
    const float* W2  = (const float*)d_in[5];
    const float* b2  = (const float*)d_in[6];
    const float* P1  = (const float*)d_in[7];
    const float* pb1 = (const float*)d_in[8];
    const float* P2  = (const float*)d_in[9];
    const float* pb2 = (const float*)d_in[10];
    const float* P3  = (const float*)d_in[11];
    const float* pb3 = (const float*)d_in[12];
    float* out = (float*)d_out;

    const int* src = ei;
    const int* dst = ei + N_EDGES;

    __half *ph1, *ph2;
    float *pz2;
    cudaGetSymbolAddress((void**)&ph1, g_h1);
    cudaGetSymbolAddress((void**)&ph2, g_h2);
    cudaGetSymbolAddress((void**)&pz2, g_z2);
    __nv_bfloat16 *pxhi, *pxlo, *pz1hi, *pz1lo, *pw1hi, *pw1lo, *pw2hi, *pw2lo;
    cudaGetSymbolAddress((void**)&pxhi,  g_xhi);
    cudaGetSymbolAddress((void**)&pxlo,  g_xlo);
    cudaGetSymbolAddress((void**)&pz1hi, g_z1hi);
    cudaGetSymbolAddress((void**)&pz1lo, g_z1lo);
    cudaGetSymbolAddress((void**)&pw1hi, g_w1hi);
    cudaGetSymbolAddress((void**)&pw1lo, g_w1lo);
    cudaGetSymbolAddress((void**)&pw2hi, g_w2hi);
    cudaGetSymbolAddress((void**)&pw2lo, g_w2lo);

    const int SM128 = 2 * 128 * (128 + 8) * 2 + 2 * 128 * 72 * 2;  // 106496
    const int SM64  = 2 * 128 * (64 + 8) * 2  + 2 * 64 * 72 * 2;   //  55296
    const int SMDEC = 2 * 128 * 72 * 2 + 6 * 64 * 72 * 2 + 512;    //  74240
    cudaFuncSetAttribute(scan_gemm1_kernel, cudaFuncAttributeMaxDynamicSharedMemorySize, SM128);
    cudaFuncSetAttribute(mma_gemm_pre<64>,  cudaFuncAttributeMaxDynamicSharedMemorySize, SM64);
    cudaFuncSetAttribute(decode_kernel,     cudaFuncAttributeMaxDynamicSharedMemorySize, SMDEC);

    const int gbN  = (N_NODES + 127) / 128;   // 391
    const int gbEL = (N_EL    + 127) / 128;   // 782
    const int gbG  = (N_NODES + 7) / 8;       // 6250

    // K1: degree count + operand splits (degi starts at 0 by invariant)
    prep_count_kernel<<<CB + XB + W1B + W2B, 256>>>(dst, x, W1, W2);
    // K2: lookback scan (+dinv) fused with gemm1; epilogue scales by dinv, emits fp16
    scan_gemm1_kernel<<<NSCAN_BLOCKS + gbN, 256, SM128>>>(pxhi, pxlo, pw1hi, pw1lo, ph1, N_NODES);
    // K3: CSR fill (byte offsets for 128B rows; restores degi=0, scanstate=0, scandone=0)
    fill_csr_kernel<<<CB, 256>>>(src, dst);
    // gather layer 1 (+bias+relu+split fused)
    gather_kernel<true><<<gbG, 256>>>(ph1, b1, nullptr);
    // conv layer 2 (epilogue scaled by dinv, fp16 out)
    mma_gemm_pre<64><<<gbN, 256, SM64>>>(pz1hi, pz1lo, pw2hi, pw2lo, ph2, N_NODES);
    gather_kernel<false><<<gbG, 256>>>(ph2, nullptr, pz2);
    // fused decode
    decode_kernel<<<gbEL, 256, SMDEC>>>(eli, b2, P1, pb1, P2, pb2, P3, pb3, out);
}

// round 15
// speedup vs baseline: 1.5980x; 1.0305x over previous
#include <cuda_runtime.h>
#include <cuda_bf16.h>
#include <cuda_fp16.h>
#include <cstdint>

#define N_NODES 50000
#define N_EDGES 800000
#define N_EL    100000
#define NSCAN_BLOCKS ((N_NODES + 255) / 256)   // 196

// ---------------- scratch (device globals; no allocation allowed) ----------------
// INVARIANT: g_degi, g_scanstate, g_scandone are zero at the start of every run.
// (zero-initialized at module load; fill_csr_kernel restores them each run)
__device__ int      g_degi     [N_NODES];
__device__ uint32_t g_scanstate[NSCAN_BLOCKS];
__device__ int      g_scandone;
__device__ int      g_rowptr   [N_NODES + 1];
__device__ int      g_csr      [N_EDGES];      // BYTE offsets: src*128 (fp16 rows)
__device__ float g_dinv[N_NODES];
__device__ __half g_h1 [N_NODES * 64];         // fp16, scaled: h1*dinv[row]
__device__ __half g_h2 [N_NODES * 64];         // fp16, scaled: h2*dinv[row]
__device__ float g_z2  [N_NODES * 64];
// pre-split bf16 operand arrays
__device__ __nv_bfloat16 g_xhi [N_NODES * 128];
__device__ __nv_bfloat16 g_xlo [N_NODES * 128];
__device__ __nv_bfloat16 g_z1hi[N_NODES * 64];
__device__ __nv_bfloat16 g_z1lo[N_NODES * 64];
__device__ __nv_bfloat16 g_w1hi[128 * 64];
__device__ __nv_bfloat16 g_w1lo[128 * 64];
__device__ __nv_bfloat16 g_w2hi[64 * 64];
__device__ __nv_bfloat16 g_w2lo[64 * 64];

// ---------------- helpers ----------------
__device__ __forceinline__ uint32_t smem_u32(const void* p) {
    uint32_t a;
    asm("{ .reg .u64 t; cvta.to.shared.u64 t, %1; cvt.u32.u64 %0, t; }" : "=r"(a) : "l"(p));
    return a;
}
__device__ __forceinline__ uint32_t pack_bf16(float x, float y) {
    __nv_bfloat162 t = __floats2bfloat162_rn(x, y);
    return *(uint32_t*)&t;
}
__device__ __forceinline__ float bf_hi(float x) {
    return __bfloat162float(__float2bfloat16_rn(x));
}
__device__ __forceinline__ void cp16(uint32_t dst, const void* src, uint32_t sz) {
    asm volatile("cp.async.ca.shared.global [%0], [%1], 16, %2;"
                 :: "r"(dst), "l"(src), "r"(sz) : "memory");
}
__device__ __forceinline__ void cp_commit_wait() {
    asm volatile("cp.async.commit_group;");
    asm volatile("cp.async.wait_group 0;" ::: "memory");
}
__device__ __forceinline__ void ldsm_x4(uint32_t* r, uint32_t addr) {
    asm volatile("ldmatrix.sync.aligned.m8n8.x4.shared.b16 {%0,%1,%2,%3}, [%4];"
                 : "=r"(r[0]), "=r"(r[1]), "=r"(r[2]), "=r"(r[3]) : "r"(addr));
}
__device__ __forceinline__ void ldsm_x4_t(uint32_t* r, uint32_t addr) {
    asm volatile("ldmatrix.sync.aligned.m8n8.x4.trans.shared.b16 {%0,%1,%2,%3}, [%4];"
                 : "=r"(r[0]), "=r"(r[1]), "=r"(r[2]), "=r"(r[3]) : "r"(addr));
}
__device__ __forceinline__ void mma_bf16(float* d, const uint32_t* a, const uint32_t* b) {
    asm volatile("mma.sync.aligned.m16n8k16.row.col.f32.bf16.bf16.f32 "
                 "{%0,%1,%2,%3}, {%4,%5,%6,%7}, {%8,%9}, {%0,%1,%2,%3};"
                 : "+f"(d[0]), "+f"(d[1]), "+f"(d[2]), "+f"(d[3])
                 : "r"(a[0]), "r"(a[1]), "r"(a[2]), "r"(a[3]), "r"(b[0]), "r"(b[1]));
}
__device__ __forceinline__ void split_store(const float* __restrict__ in,
                                            __nv_bfloat16* __restrict__ hi,
                                            __nv_bfloat16* __restrict__ lo, int i) {
    float4 v = ((const float4*)in)[i];
    float hx = bf_hi(v.x), hy = bf_hi(v.y), hz = bf_hi(v.z), hw = bf_hi(v.w);
    ((uint2*)hi)[i] = make_uint2(pack_bf16(hx, hy), pack_bf16(hz, hw));
    ((uint2*)lo)[i] = make_uint2(pack_bf16(v.x - hx, v.y - hy), pack_bf16(v.z - hz, v.w - hw));
}
__device__ __forceinline__ int warp_incl_scan(int v, int lane) {
    #pragma unroll
    for (int o = 1; o < 32; o <<= 1) {
        int t = __shfl_up_sync(0xffffffffu, v, o);
        if (lane >= o) v += t;
    }
    return v;
}

// ---------------- K1: degree count + all operand splits (range-dispatched) ----------------
#define CB  ((N_EDGES + 255) / 256)          // 3125 blocks: count degrees
#define XB  ((N_NODES * 32 + 255) / 256)     // 6250 blocks: split x
#define W1B ((128 * 16 + 255) / 256)         // 8 blocks
#define W2B ((64 * 16 + 255) / 256)          // 4 blocks
__global__ void prep_count_kernel(const int* __restrict__ dst, const float* __restrict__ x,
                                  const float* __restrict__ W1, const float* __restrict__ W2) {
    int b = blockIdx.x;
    if (b < CB) {
        int e = b * 256 + threadIdx.x;
        if (e < N_EDGES) atomicAdd(&g_degi[dst[e]], 1);   // degi starts at 0 (invariant)
    } else if (b < CB + XB) {
        int i = (b - CB) * 256 + threadIdx.x;
        if (i < N_NODES * 32) split_store(x, g_xhi, g_xlo, i);
    } else if (b < CB + XB + W1B) {
        int i = (b - CB - XB) * 256 + threadIdx.x;
        if (i < 128 * 16) split_store(W1, g_w1hi, g_w1lo, i);
    } else {
        int i = (b - CB - XB - W1B) * 256 + threadIdx.x;
        if (i < 64 * 16) split_store(W2, g_w2hi, g_w2lo, i);
    }
}

// ---------------- K2: decoupled-lookback scan (+dinv) fused with gemm1 ----------------
#define FLAG_AGG (1u << 30)
#define FLAG_PRE (2u << 30)
#define VAL_MASK 0x3FFFFFFFu

__device__ __forceinline__ void scan_block_body(int b) {
    __shared__ int wsum[8];
    __shared__ int s_base;
    int i = b * 256 + threadIdx.x;
    int lane = threadIdx.x & 31, w = threadIdx.x >> 5;

    int d = (i < N_NODES) ? g_degi[i] : 0;
    if (i < N_NODES) g_dinv[i] = rsqrtf((float)d + 1.0f);   // +1 = self-loop
    int s = warp_incl_scan(d, lane);
    if (lane == 31) wsum[w] = s;
    __syncthreads();
    if (w == 0) {
        int ws = (lane < 8) ? wsum[lane] : 0;
        ws = warp_incl_scan(ws, lane);
        if (lane < 8) wsum[lane] = ws;
    }
    __syncthreads();
    int base = (w > 0) ? wsum[w - 1] : 0;
    int incl = base + s;                 // inclusive within block
    uint32_t blocksum = (uint32_t)wsum[7];

    if (threadIdx.x == 0) {
        if (b == 0) {
            atomicExch(&g_scanstate[0], FLAG_PRE | blocksum);
            s_base = 0;
        } else {
            atomicExch(&g_scanstate[b], FLAG_AGG | blocksum);
        }
    }
    if (b > 0 && w == 0) {               // warp 0 lookback
        uint32_t exc = 0;
        int look = b - 1;
        while (true) {
            int idx = look - lane;
            uint32_t f = 0, val = 0;
            if (idx >= 0) {
                uint32_t v;
                do { v = atomicAdd(&g_scanstate[idx], 0u); } while ((v >> 30) == 0u);
                f = v >> 30;
                val = v & VAL_MASK;
            }
            unsigned pm = __ballot_sync(0xffffffffu, f == 2u);
            if (pm) {
                int cut = __ffs(pm) - 1;
                if (lane > cut) val = 0;
            }
            #pragma unroll
            for (int o = 16; o > 0; o >>= 1) val += __shfl_xor_sync(0xffffffffu, val, o);
            exc += val;
            if (pm) break;
            look -= 32;
        }
        if (lane == 0) {
            s_base = (int)exc;
            atomicExch(&g_scanstate[b], FLAG_PRE | (exc + blocksum));
        }
    }
    __syncthreads();
    if (i < N_NODES) g_rowptr[i] = s_base + incl - d;       // exclusive
    if (i == 0) g_rowptr[N_NODES] = N_EDGES;
    // signal dinv/rowptr complete (gemm epilogues wait on this)
    __syncthreads();
    if (threadIdx.x == 0) {
        __threadfence();
        atomicAdd(&g_scandone, 1);
    }
}

__global__ __launch_bounds__(256)
void scan_gemm1_kernel(const __nv_bfloat16* __restrict__ Ahi, const __nv_bfloat16* __restrict__ Alo,
                       const __nv_bfloat16* __restrict__ Bhi, const __nv_bfloat16* __restrict__ Blo,
                       __half* __restrict__ C, int M)
{
    if (blockIdx.x < NSCAN_BLOCKS) { scan_block_body(blockIdx.x); return; }

    constexpr int K = 128;
    constexpr int SA_H = K + 8;
    constexpr int SB_H = 72;
    constexpr int A_HI = 0;
    constexpr int A_LO = 128 * SA_H * 2;
    constexpr int B_HI = 2 * 128 * SA_H * 2;
    constexpr int B_LO = B_HI + K * SB_H * 2;

    extern __shared__ char smem[];
    const uint32_t sbase = smem_u32(smem);
    const int tid  = threadIdx.x;
    const int wid  = tid >> 5;
    const int lane = tid & 31;
    const int row0 = (blockIdx.x - NSCAN_BLOCKS) * 128;

    constexpr int ACH = K / 8;
    #pragma unroll
    for (int idx = tid; idx < 128 * ACH; idx += 256) {
        int r  = idx / ACH;
        int kc = (idx - r * ACH) * 8;
        int row = row0 + r;
        uint32_t sz = (row < M) ? 16u : 0u;
        size_t goff = (size_t)(row < M ? row : 0) * K + kc;
        uint32_t d = sbase + A_HI + (uint32_t)(r * SA_H + kc) * 2;
        cp16(d,                 &Ahi[goff], sz);
        cp16(d + (A_LO - A_HI), &Alo[goff], sz);
    }
    #pragma unroll
    for (int idx = tid; idx < K * 8; idx += 256) {
        int k = idx >> 3, nc = (idx & 7) * 8;
        uint32_t d = sbase + B_HI + (uint32_t)(k * SB_H + nc) * 2;
        cp16(d,                 &Bhi[k * 64 + nc], 16u);
        cp16(d + (B_LO - B_HI), &Blo[k * 64 + nc], 16u);
    }
    cp_commit_wait();
    __syncthreads();

    const int wm = (wid & 3) * 32;
    const int wn = (wid >> 2) * 32;
    const int lrow = lane & 15;
    const int lsel = (lane >> 4) * 8;

    float acc[2][4][4];
    #pragma unroll
    for (int mt = 0; mt < 2; mt++)
        #pragma unroll
        for (int nt = 0; nt < 4; nt++)
            #pragma unroll
            for (int i = 0; i < 4; i++) acc[mt][nt][i] = 0.f;

    #pragma unroll
    for (int k0 = 0; k0 < K; k0 += 16) {
        uint32_t a_hi[2][4], a_lo[2][4];
        #pragma unroll
        for (int mt = 0; mt < 2; mt++) {
            uint32_t off = (uint32_t)((wm + 16 * mt + lrow) * SA_H + k0 + lsel) * 2;
            ldsm_x4(a_hi[mt], sbase + A_HI + off);
            ldsm_x4(a_lo[mt], sbase + A_LO + off);
        }
        uint32_t b_hi[2][4], b_lo[2][4];
        #pragma unroll
        for (int h = 0; h < 2; h++) {
            uint32_t off = (uint32_t)((k0 + lrow) * SB_H + wn + 16 * h + lsel) * 2;
            ldsm_x4_t(b_hi[h], sbase + B_HI + off);
            ldsm_x4_t(b_lo[h], sbase + B_LO + off);
        }
        #pragma unroll
        for (int mt = 0; mt < 2; mt++)
            #pragma unroll
            for (int nt = 0; nt < 4; nt++) {
                const uint32_t* bh = &b_hi[nt >> 1][(nt & 1) * 2];
                const uint32_t* bl = &b_lo[nt >> 1][(nt & 1) * 2];
                mma_bf16(acc[mt][nt], a_hi[mt], bh);
                mma_bf16(acc[mt][nt], a_hi[mt], bl);
                mma_bf16(acc[mt][nt], a_lo[mt], bh);
            }
    }

    // wait for scan blocks (dinv ready); one thread spins, all sync after
    __shared__ int s_ready;
    if (tid == 0) {
        while (atomicAdd(&g_scandone, 0) < NSCAN_BLOCKS) {}
        __threadfence();
        s_ready = 1;
    }
    __syncthreads();

    const int g  = lane >> 2;
    const int tg = lane & 3;
    #pragma unroll
    for (int mt = 0; mt < 2; mt++)
        #pragma unroll
        for (int rh = 0; rh < 2; rh++) {
            int row = row0 + wm + 16 * mt + g + 8 * rh;
            if (row >= M) continue;
            float di = g_dinv[row];
            #pragma unroll
            for (int nt = 0; nt < 4; nt++) {
                int col = wn + 8 * nt + 2 * tg;
                ((__half2*)C)[row * 32 + (col >> 1)] =
                    __floats2half2_rn(acc[mt][nt][2 * rh] * di, acc[mt][nt][2 * rh + 1] * di);
            }
        }
}

// ---------------- K3: fill CSR (byte offsets for 128B fp16 rows; restores invariants) ----------------
__global__ void fill_csr_kernel(const int* __restrict__ src, const int* __restrict__ dst) {
    int e = blockIdx.x * 256 + threadIdx.x;
    if (blockIdx.x == 0) {
        if (threadIdx.x < NSCAN_BLOCKS) g_scanstate[threadIdx.x] = 0u;
        if (threadIdx.x == 0) g_scandone = 0;
    }
    if (e >= N_EDGES) return;
    int d = dst[e];
    int old = atomicSub(&g_degi[d], 1);      // degi returns to 0 after this kernel
    g_csr[g_rowptr[d] + old - 1] = src[e] << 7;   // byte offset: src*128
}

// ---------------- pre-split mma GEMM (layer 2), epilogue scaled by dinv, fp16 out ----------------
template<int K>
__global__ __launch_bounds__(256)
void mma_gemm_pre(const __nv_bfloat16* __restrict__ Ahi, const __nv_bfloat16* __restrict__ Alo,
                  const __nv_bfloat16* __restrict__ Bhi, const __nv_bfloat16* __restrict__ Blo,
                  __half* __restrict__ C, int M)
{
    constexpr int SA_H = K + 8;
    constexpr int SB_H = 72;
    constexpr int A_HI = 0;
    constexpr int A_LO = 128 * SA_H * 2;
    constexpr int B_HI = 2 * 128 * SA_H * 2;
    constexpr int B_LO = B_HI + K * SB_H * 2;

    extern __shared__ char smem[];
    const uint32_t sbase = smem_u32(smem);
    const int tid  = threadIdx.x;
    const int wid  = tid >> 5;
    const int lane = tid & 31;
    const int row0 = blockIdx.x * 128;

    constexpr int ACH = K / 8;
    #pragma unroll
    for (int idx = tid; idx < 128 * ACH; idx += 256) {
        int r  = idx / ACH;
        int kc = (idx - r * ACH) * 8;
        int row = row0 + r;
        uint32_t sz = (row < M) ? 16u : 0u;
        size_t goff = (size_t)(row < M ? row : 0) * K + kc;
        uint32_t d = sbase + A_HI + (uint32_t)(r * SA_H + kc) * 2;
        cp16(d,                 &Ahi[goff], sz);
        cp16(d + (A_LO - A_HI), &Alo[goff], sz);
    }
    #pragma unroll
    for (int idx = tid; idx < K * 8; idx += 256) {
        int k = idx >> 3, nc = (idx & 7) * 8;
        uint32_t d = sbase + B_HI + (uint32_t)(k * SB_H + nc) * 2;
        cp16(d,                 &Bhi[k * 64 + nc], 16u);
        cp16(d + (B_LO - B_HI), &Blo[k * 64 + nc], 16u);
    }
    cp_commit_wait();
    __syncthreads();

    const int wm = (wid & 3) * 32;
    const int wn = (wid >> 2) * 32;
    const int lrow = lane & 15;
    const int lsel = (lane >> 4) * 8;

    float acc[2][4][4];
    #pragma unroll
    for (int mt = 0; mt < 2; mt++)
        #pragma unroll
        for (int nt = 0; nt < 4; nt++)
            #pragma unroll
            for (int i = 0; i < 4; i++) acc[mt][nt][i] = 0.f;

    #pragma unroll
    for (int k0 = 0; k0 < K; k0 += 16) {
        uint32_t a_hi[2][4], a_lo[2][4];
        #pragma unroll
        for (int mt = 0; mt < 2; mt++) {
            uint32_t off = (uint32_t)((wm + 16 * mt + lrow) * SA_H + k0 + lsel) * 2;
            ldsm_x4(a_hi[mt], sbase + A_HI + off);
            ldsm_x4(a_lo[mt], sbase + A_LO + off);
        }
        uint32_t b_hi[2][4], b_lo[2][4];
        #pragma unroll
        for (int h = 0; h < 2; h++) {
            uint32_t off = (uint32_t)((k0 + lrow) * SB_H + wn + 16 * h + lsel) * 2;
            ldsm_x4_t(b_hi[h], sbase + B_HI + off);
            ldsm_x4_t(b_lo[h], sbase + B_LO + off);
        }
        #pragma unroll
        for (int mt = 0; mt < 2; mt++)
            #pragma unroll
            for (int nt = 0; nt < 4; nt++) {
                const uint32_t* bh = &b_hi[nt >> 1][(nt & 1) * 2];
                const uint32_t* bl = &b_lo[nt >> 1][(nt & 1) * 2];
                mma_bf16(acc[mt][nt], a_hi[mt], bh);
                mma_bf16(acc[mt][nt], a_hi[mt], bl);
                mma_bf16(acc[mt][nt], a_lo[mt], bh);
            }
    }

    const int g  = lane >> 2;
    const int tg = lane & 3;
    #pragma unroll
    for (int mt = 0; mt < 2; mt++)
        #pragma unroll
        for (int rh = 0; rh < 2; rh++) {
            int row = row0 + wm + 16 * mt + g + 8 * rh;
            if (row >= M) continue;
            float di = g_dinv[row];
            #pragma unroll
            for (int nt = 0; nt < 4; nt++) {
                int col = wn + 8 * nt + 2 * tg;
                ((__half2*)C)[row * 32 + (col >> 1)] =
                    __floats2half2_rn(acc[mt][nt][2 * rh] * di, acc[mt][nt][2 * rh + 1] * di);
            }
        }
}

// ---------------- CSR gather (fp16 rows, pairwise HADD2 pre-reduce) ----------------
// out = dd*(Σ h'[s] + h'[node]),  h' pre-scaled by dinv[row]
template<bool LAYER1>
__global__ __launch_bounds__(256)
void gather_kernel(const __half* __restrict__ h, const float* __restrict__ bias,
                   float* __restrict__ zout)
{
    int node = blockIdx.x * 8 + (threadIdx.x >> 5);   // warp per node
    int lane = threadIdx.x & 31;
    if (node >= N_NODES) return;

    const char* hp = (const char*)h + lane * 4;       // lane-fixed base (half2 per lane)
    float2 a0 = __half22float2(*(const __half2*)(hp + (size_t)node * 128));  // self-loop
    float2 a1 = make_float2(0.f, 0.f);

    int e   = __ldg(&g_rowptr[node]);
    int end = __ldg(&g_rowptr[node + 1]);
    for (; e + 3 < end; e += 4) {
        int o0 = __ldg(&g_csr[e]);
        int o1 = __ldg(&g_csr[e + 1]);
        int o2 = __ldg(&g_csr[e + 2]);
        int o3 = __ldg(&g_csr[e + 3]);
        __half2 v0 = *(const __half2*)(hp + o0);
        __half2 v1 = *(const __half2*)(hp + o1);
        __half2 v2 = *(const __half2*)(hp + o2);
        __half2 v3 = *(const __half2*)(hp + o3);
        float2 f01 = __half22float2(__hadd2(v0, v1));   // one fp16 add per pair
        float2 f23 = __half22float2(__hadd2(v2, v3));
        a0.x += f01.x; a0.y += f01.y;
        a1.x += f23.x; a1.y += f23.y;
    }
    for (; e < end; e++) {
        int o = __ldg(&g_csr[e]);
        float2 v = __half22float2(*(const __half2*)(hp + o));
        a0.x += v.x; a0.y += v.y;
    }
    float dd = g_dinv[node];
    float2 acc = make_float2((a0.x + a1.x) * dd, (a0.y + a1.y) * dd);

    if (LAYER1) {
        float2 b = *(const float2*)&bias[lane * 2];
        float vx = fmaxf(acc.x + b.x, 0.f);
        float vy = fmaxf(acc.y + b.y, 0.f);
        float hx = bf_hi(vx), hy = bf_hi(vy);
        ((uint32_t*)g_z1hi)[node * 32 + lane] = pack_bf16(hx, hy);
        ((uint32_t*)g_z1lo)[node * 32 + lane] = pack_bf16(vx - hx, vy - hy);
    } else {
        *(float2*)&zout[(size_t)node * 64 + lane * 2] = acc;
    }
}

// ---------------- fused decode: ef -> P1+relu -> P2+relu -> P3 dot ----------------
__global__ __launch_bounds__(256)
void decode_kernel(const int* __restrict__ eli, const float* __restrict__ b2,
                   const float* __restrict__ P1, const float* __restrict__ pb1,
                   const float* __restrict__ P2, const float* __restrict__ pb2,
                   const float* __restrict__ P3, const float* __restrict__ pb3,
                   float* __restrict__ out)
{
    constexpr int SA_H = 72, SB_H = 72;
    constexpr int EF_HI = 0;
    constexpr int EF_LO = 128 * SA_H * 2;
    constexpr int P1_HI = 2 * 128 * SA_H * 2;
    constexpr int P1_LO = P1_HI + 64 * SB_H * 2;
    constexpr int P2_HI = P1_LO + 64 * SB_H * 2;
    constexpr int P2_LO = P2_HI + 64 * SB_H * 2;
    constexpr int S_OUT = P2_LO + 64 * SB_H * 2;

    extern __shared__ char smem[];
    const uint32_t sbase = smem_u32(smem);
    const int tid  = threadIdx.x;
    const int wid  = tid >> 5;
    const int lane = tid & 31;
    const int row0 = blockIdx.x * 128;

    if (tid < 128) *(float*)(smem + S_OUT + tid * 4) = 0.f;

    #pragma unroll
    for (int idx = tid; idx < 128 * 16; idx += 256) {
        int pl = idx >> 4, c4 = (idx & 15) << 2;
        int p = row0 + pl;
        float4 r = make_float4(0.f, 0.f, 0.f, 0.f);
        if (p < N_EL) {
            int a = __ldg(&eli[p]);
            int b = __ldg(&eli[N_EL + p]);
            float4 bb = *(const float4*)&b2[c4];
            float4 za = *(const float4*)&g_z2[a * 64 + c4];
            float4 zb = *(const float4*)&g_z2[b * 64 + c4];
            r.x = (za.x + bb.x) * (zb.x + bb.x);
            r.y = (za.y + bb.y) * (zb.y + bb.y);
            r.z = (za.z + bb.z) * (zb.z + bb.z);
            r.w = (za.w + bb.w) * (zb.w + bb.w);
        }
        float hx = bf_hi(r.x), hy = bf_hi(r.y), hz = bf_hi(r.z), hw = bf_hi(r.w);
        uint32_t off = (uint32_t)(pl * SA_H + c4) * 2;
        *(uint2*)(smem + EF_HI + off) = make_uint2(pack_bf16(hx, hy), pack_bf16(hz, hw));
        *(uint2*)(smem + EF_LO + off) = make_uint2(pack_bf16(r.x - hx, r.y - hy),
                                                   pack_bf16(r.z - hz, r.w - hw));
    }
    #pragma unroll
    for (int idx = tid; idx < 64 * 16; idx += 256) {
        int k = idx >> 4, nc = (idx & 15) << 2;
        uint32_t off = (uint32_t)(k * SB_H + nc) * 2;
        float4 v = *(const float4*)&P1[k * 64 + nc];
        float hx = bf_hi(v.x), hy = bf_hi(v.y), hz = bf_hi(v.z), hw = bf_hi(v.w);
        *(uint2*)(smem + P1_HI + off) = make_uint2(pack_bf16(hx, hy), pack_bf16(hz, hw));
        *(uint2*)(smem + P1_LO + off) = make_uint2(pack_bf16(v.x - hx, v.y - hy),
                                                   pack_bf16(v.z - hz, v.w - hw));
        float4 u = *(const float4*)&P2[k * 64 + nc];
        float ux = bf_hi(u.x), uy = bf_hi(u.y), uz = bf_hi(u.z), uw = bf_hi(u.w);
        *(uint2*)(smem + P2_HI + off) = make_uint2(pack_bf16(ux, uy), pack_bf16(uz, uw));
        *(uint2*)(smem + P2_LO + off) = make_uint2(pack_bf16(u.x - ux, u.y - uy),
                                                   pack_bf16(u.z - uz, u.w - uw));
    }
    __syncthreads();

    const int wm = (wid & 3) * 32;
    const int wn = (wid >> 2) * 32;
    const int lrow = lane & 15;
    const int lsel = (lane >> 4) * 8;
    const int g  = lane >> 2;
    const int tg = lane & 3;

    float acc[2][4][4];
    #pragma unroll
    for (int mt = 0; mt < 2; mt++)
        #pragma unroll
        for (int nt = 0; nt < 4; nt++)
            #pragma unroll
            for (int i = 0; i < 4; i++) acc[mt][nt][i] = 0.f;

    #pragma unroll
    for (int k0 = 0; k0 < 64; k0 += 16) {
        uint32_t a_hi[2][4], a_lo[2][4];
        #pragma unroll
        for (int mt = 0; mt < 2; mt++) {
            uint32_t off = (uint32_t)((wm + 16 * mt + lrow) * SA_H + k0 + lsel) * 2;
            ldsm_x4(a_hi[mt], sbase + EF_HI + off);
            ldsm_x4(a_lo[mt], sbase + EF_LO + off);
        }
        uint32_t b_hi[2][4], b_lo[2][4];
        #pragma unroll
        for (int h = 0; h < 2; h++) {
            uint32_t off = (uint32_t)((k0 + lrow) * SB_H + wn + 16 * h + lsel) * 2;
            ldsm_x4_t(b_hi[h], sbase + P1_HI + off);
            ldsm_x4_t(b_lo[h], sbase + P1_LO + off);
        }
        #pragma unroll
        for (int mt = 0; mt < 2; mt++)
            #pragma unroll
            for (int nt = 0; nt < 4; nt++) {
                const uint32_t* bh = &b_hi[nt >> 1][(nt & 1) * 2];
                const uint32_t* bl = &b_lo[nt >> 1][(nt & 1) * 2];
                mma_bf16(acc[mt][nt], a_hi[mt], bh);
                mma_bf16(acc[mt][nt], a_hi[mt], bl);
                mma_bf16(acc[mt][nt], a_lo[mt], bh);
            }
    }
    __syncthreads();

    #pragma unroll
    for (int mt = 0; mt < 2; mt++)
        #pragma unroll
        for (int rh = 0; rh < 2; rh++) {
            int rl = wm + 16 * mt + g + 8 * rh;
            #pragma unroll
            for (int nt = 0; nt < 4; nt++) {
                int col = wn + 8 * nt + 2 * tg;
                float vx = fmaxf(acc[mt][nt][2 * rh]     + __ldg(&pb1[col]),     0.f);
                float vy = fmaxf(acc[mt][nt][2 * rh + 1] + __ldg(&pb1[col + 1]), 0.f);
                float hx = bf_hi(vx), hy = bf_hi(vy);
                uint32_t off = (uint32_t)(rl * SA_H + col) * 2;
                *(uint32_t*)(smem + EF_HI + off) = pack_bf16(hx, hy);
                *(uint32_t*)(smem + EF_LO + off) = pack_bf16(vx - hx, vy - hy);
            }
        }
    __syncthreads();

    #pragma unroll
    for (int mt = 0; mt < 2; mt++)
        #pragma unroll
        for (int nt = 0; nt < 4; nt++)
            #pragma unroll
            for (int i = 0; i < 4; i++) acc[mt][nt][i] = 0.f;

    #pragma unroll
    for (int k0 = 0; k0 < 64; k0 += 16) {
        uint32_t a_hi[2][4], a_lo[2][4];
        #pragma unroll
        for (int mt = 0; mt < 2; mt++) {
            uint32_t off = (uint32_t)((wm + 16 * mt + lrow) * SA_H + k0 + lsel) * 2;
            ldsm_x4(a_hi[mt], sbase + EF_HI + off);
            ldsm_x4(a_lo[mt], sbase + EF_LO + off);
        }
        uint32_t b_hi[2][4], b_lo[2][4];
        #pragma unroll
        for (int h = 0; h < 2; h++) {
            uint32_t off = (uint32_t)((k0 + lrow) * SB_H + wn + 16 * h + lsel) * 2;
            ldsm_x4_t(b_hi[h], sbase + P2_HI + off);
            ldsm_x4_t(b_lo[h], sbase + P2_LO + off);
        }
        #pragma unroll
        for (int mt = 0; mt < 2; mt++)
            #pragma unroll
            for (int nt = 0; nt < 4; nt++) {
                const uint32_t* bh = &b_hi[nt >> 1][(nt & 1) * 2];
                const uint32_t* bl = &b_lo[nt >> 1][(nt & 1) * 2];
                mma_bf16(acc[mt][nt], a_hi[mt], bh);
                mma_bf16(acc[mt][nt], a_hi[mt], bl);
                mma_bf16(acc[mt][nt], a_lo[mt], bh);
            }
    }

    #pragma unroll
    for (int mt = 0; mt < 2; mt++)
        #pragma unroll
        for (int rh = 0; rh < 2; rh++) {
            float s = 0.f;
            #pragma unroll
            for (int nt = 0; nt < 4; nt++) {
                int col = wn + 8 * nt + 2 * tg;
                float vx = fmaxf(acc[mt][nt][2 * rh]     + __ldg(&pb2[col]),     0.f);
                float vy = fmaxf(acc[mt][nt][2 * rh + 1] + __ldg(&pb2[col + 1]), 0.f);
                s += vx * __ldg(&P3[col]) + vy * __ldg(&P3[col + 1]);
            }
            s += __shfl_xor_sync(0xffffffffu, s, 1);
            s += __shfl_xor_sync(0xffffffffu, s, 2);
            if (tg == 0) {
                int rl = wm + 16 * mt + g + 8 * rh;
                atomicAdd((float*)(smem + S_OUT) + rl, s);
            }
        }
    __syncthreads();
    if (tid < 128) {
        int p = row0 + tid;
        if (p < N_EL) out[p] = *(float*)(smem + S_OUT + tid * 4) + __ldg(&pb3[0]);
    }
}

// ---------------- launcher ----------------
extern "C" void kernel_launch(void* const* d_in, const int* in_sizes, int n_in,
                              void* d_out, int out_size)
{
    const float* x   = (const float*)d_in[0];
    const int*   ei  = (const int*)  d_in[1];
    const int*   eli = (const int*)  d_in[2];
    const float* W1  = (const float*)d_in[3];
    const float* b1  = (const float*)d_in[4];
    const float* W2  = (const float*)d_in[5];
    const float* b2  = (const float*)d_in[6];
    const float* P1  = (const float*)d_in[7];
    const float* pb1 = (const float*)d_in[8];
    const float* P2  = (const float*)d_in[9];
    const float* pb2 = (const float*)d_in[10];
    const float* P3  = (const float*)d_in[11];
    const float* pb3 = (const float*)d_in[12];
    float* out = (float*)d_out;

    const int* src = ei;
    const int* dst = ei + N_EDGES;

    __half *ph1, *ph2;
    float *pz2;
    cudaGetSymbolAddress((void**)&ph1, g_h1);
    cudaGetSymbolAddress((void**)&ph2, g_h2);
    cudaGetSymbolAddress((void**)&pz2, g_z2);
    __nv_bfloat16 *pxhi, *pxlo, *pz1hi, *pz1lo, *pw1hi, *pw1lo, *pw2hi, *pw2lo;
    cudaGetSymbolAddress((void**)&pxhi,  g_xhi);
    cudaGetSymbolAddress((void**)&pxlo,  g_xlo);
    cudaGetSymbolAddress((void**)&pz1hi, g_z1hi);
    cudaGetSymbolAddress((void**)&pz1lo, g_z1lo);
    cudaGetSymbolAddress((void**)&pw1hi, g_w1hi);
    cudaGetSymbolAddress((void**)&pw1lo, g_w1lo);
    cudaGetSymbolAddress((void**)&pw2hi, g_w2hi);
    cudaGetSymbolAddress((void**)&pw2lo, g_w2lo);

    const int SM128 = 2 * 128 * (128 + 8) * 2 + 2 * 128 * 72 * 2;  // 106496
    const int SM64  = 2 * 128 * (64 + 8) * 2  + 2 * 64 * 72 * 2;   //  55296
    const int SMDEC = 2 * 128 * 72 * 2 + 6 * 64 * 72 * 2 + 512;    //  74240
    cudaFuncSetAttribute(scan_gemm1_kernel, cudaFuncAttributeMaxDynamicSharedMemorySize, SM128);
    cudaFuncSetAttribute(mma_gemm_pre<64>,  cudaFuncAttributeMaxDynamicSharedMemorySize, SM64);
    cudaFuncSetAttribute(decode_kernel,     cudaFuncAttributeMaxDynamicSharedMemorySize, SMDEC);

    const int gbN  = (N_NODES + 127) / 128;   // 391
    const int gbEL = (N_EL    + 127) / 128;   // 782
    const int gbG  = (N_NODES + 7) / 8;       // 6250

    // K1: degree count + operand splits (degi starts at 0 by invariant)
    prep_count_kernel<<<CB + XB + W1B + W2B, 256>>>(dst, x, W1, W2);
    // K2: lookback scan (+dinv) fused with gemm1; epilogue scales by dinv, emits fp16
    scan_gemm1_kernel<<<NSCAN_BLOCKS + gbN, 256, SM128>>>(pxhi, pxlo, pw1hi, pw1lo, ph1, N_NODES);
    // K3: CSR fill (byte offsets for 128B rows; restores degi=0, scanstate=0, scandone=0)
    fill_csr_kernel<<<CB, 256>>>(src, dst);
    // gather layer 1 (+bias+relu+split fused)
    gather_kernel<true><<<gbG, 256>>>(ph1, b1, nullptr);
    // conv layer 2 (epilogue scaled by dinv, fp16 out)
    mma_gemm_pre<64><<<gbN, 256, SM64>>>(pz1hi, pz1lo, pw2hi, pw2lo, ph2, N_NODES);
    gather_kernel<false><<<gbG, 256>>>(ph2, nullptr, pz2);
    // fused decode
    decode_kernel<<<gbEL, 256, SMDEC>>>(eli, b2, P1, pb1, P2, pb2, P3, pb3, out);
}